// round 9
// baseline (speedup 1.0000x reference)
#include <cuda_runtime.h>

#define BB    8
#define NPTS  4096
#define KNN   20
#define TOTPTS (BB*NPTS)

// ---------------- static device scratch (sanctioned workaround) ----------------
static __device__ float g_pair[(size_t)BB*NPTS*NPTS]; // 512MB: all 8 batches' pair matrices
static __device__ float g_h  [TOTPTS*64];   // features after conv1+conv2, (B,N,64)
static __device__ float g_nh [TOTPTS];      // ||h||^2
static __device__ float g_nx [TOTPTS];      // ||x||^2
static __device__ int   g_idx1[TOTPTS*KNN];
static __device__ int   g_idx2[TOTPTS*KNN];
static __device__ float g_a  [TOTPTS*64];   // (Wc-Wd)@h
static __device__ float g_u  [TOTPTS*64];   // Wd@h
static __device__ float g_hdg[TOTPTS*64];   // after dg branch max
static __device__ float g_p2 [TOTPTS*64];   // sn-branch per-point MLP output
static __device__ float g_hsn[TOTPTS*64];   // after sn gather-max (then conv3 in-place)
static __device__ float g_h4 [TOTPTS*128];  // after conv4

__device__ __forceinline__ float lrelu(float v){ return fmaxf(v, 0.01f*v); }

// reference-order epilogue (identical codegen at every use site)
__device__ __forceinline__ float epi(float acc, float rn, float cn){
    return 2.f*acc - rn - cn;
}

__device__ __forceinline__ unsigned f2ord(float f){
    unsigned u = __float_as_uint(f);
    return (u & 0x80000000u) ? ~u : (u | 0x80000000u);
}

__device__ __forceinline__ const float* pconv_in(int sel){
    switch(sel){ case 0: return g_h; case 1: return g_hdg; case 2: return g_p2;
                 case 3: return g_hsn; default: return g_hsn; }
}
__device__ __forceinline__ float* pconv_out(int sel){
    switch(sel){ case 0: return g_h; case 1: return g_p2; case 2: return g_p2;
                 case 3: return g_hsn; default: return g_h4; }
}

// ---------------- conv1: x(B,N,3) -> g_h (64ch) ----------------
__global__ void k_conv1(const float* __restrict__ x, const float* __restrict__ w,
                        const float* __restrict__ g, const float* __restrict__ b)
{
    __shared__ float sw[192], sg[64], sb[64];
    int t = threadIdx.x;
    if (t < 192) sw[t] = w[t];
    if (t < 64){ sg[t] = g[t]; sb[t] = b[t]; }
    __syncthreads();
    int lp = t >> 6, c = t & 63;
    int p  = blockIdx.x*4 + lp;
    float x0 = x[p*3+0], x1 = x[p*3+1], x2 = x[p*3+2];
    float v = sw[c*3+0]*x0 + sw[c*3+1]*x1 + sw[c*3+2]*x2;
    g_h[p*64+c] = lrelu(v*sg[c] + sb[c]);
}

// ---------------- pointwise conv 64 -> COUT with BN+LReLU; 8 point-groups per block ----------------
template<int COUT>
__global__ void k_pconv(int sel, const float* __restrict__ w,
                        const float* __restrict__ g, const float* __restrict__ b)
{
    const int PPB = 256/COUT;
    const int GRP = 8;
    __shared__ float wt[64*COUT];
    __shared__ float hs[PPB][64];
    __shared__ float sg[COUT], sb[COUT];
    const float* in  = pconv_in(sel);
    float*       out = pconv_out(sel);
    int t = threadIdx.x;
    for (int i = t; i < 64*COUT; i += 256){ int c = i>>6, k = i&63; wt[k*COUT+c] = w[i]; }
    for (int i = t; i < COUT;    i += 256){ sg[i] = g[i]; sb[i] = b[i]; }
    __syncthreads();
    int lp = t / COUT, c = t % COUT;
    float wr[64];
    #pragma unroll
    for (int k = 0; k < 64; k++) wr[k] = wt[k*COUT+c];
    float G = sg[c], Bv = sb[c];
    for (int g2 = 0; g2 < GRP; g2++){
        int p = (blockIdx.x*GRP + g2)*PPB + lp;
        __syncthreads();
        if (c < 64) hs[lp][c] = in[p*64+c];
        __syncthreads();
        float s = 0.f;
        #pragma unroll
        for (int k = 0; k < 64; k++) s += wr[k]*hs[lp][k];
        out[p*COUT+c] = lrelu(s*G + Bv);
    }
}

// ---------------- squared norms ----------------
__global__ void k_norms(const float* __restrict__ x)
{
    int p = blockIdx.x*256 + threadIdx.x;
    const float* hp = &g_h[p*64];
    float s = 0.f;
    #pragma unroll
    for (int k = 0; k < 64; k++){ float v = hp[k]; s += v*v; }
    g_nh[p] = s;
    float x0 = x[p*3], x1 = x[p*3+1], x2 = x[p*3+2];
    float sx = 0.f;
    sx = fmaf(x0,x0,sx); sx = fmaf(x1,x1,sx); sx = fmaf(x2,x2,sx);
    g_nx[p] = sx;
}

// ---------------- feature pair matrix: 128x128 tiles, 8x8 per thread,
//                  triangular over 32x32 tile grid; mirror via raw-dot smem staging ----------------
__global__ void __launch_bounds__(256, 2) k_pair(void)
{
    __shared__ float sBuf[2*32*132];
    float (*sA)[132] = (float(*)[132])sBuf;
    float (*sB)[132] = (float(*)[132])(sBuf + 32*132);
    float (*sM)[132] = (float(*)[132])sBuf;   // mirror staging alias (64 rows x 128 cols)

    int b = blockIdx.y;
    const float* A  = g_h + (size_t)b*NPTS*64;
    const float* nn = g_nh + b*NPTS;
    float* pair = g_pair + (size_t)b*NPTS*NPTS;
    int t = threadIdx.x;

    int u = blockIdx.x;
    int bi = 0, rem = 32;
    while (u >= rem){ u -= rem; rem--; bi++; }
    int bj = bi + u;
    int r0 = bi*128, c0 = bj*128;

    int ty = t >> 4, tx = t & 15;
    float acc[8][8];
    #pragma unroll
    for (int i = 0; i < 8; i++)
        #pragma unroll
        for (int j = 0; j < 8; j++) acc[i][j] = 0.f;

    for (int kc = 0; kc < 2; kc++){
        __syncthreads();
        for (int i = t; i < 128*32; i += 256){
            int r = i >> 5, c = i & 31;
            sA[c][r] = A[(size_t)(r0+r)*64 + kc*32 + c];
        }
        for (int i = t; i < 128*32; i += 256){
            int r = i >> 5, c = i & 31;
            sB[c][r] = A[(size_t)(c0+r)*64 + kc*32 + c];
        }
        __syncthreads();
        #pragma unroll
        for (int c = 0; c < 32; c++){
            float4 a0 = *(const float4*)&sA[c][ty*4];
            float4 a1 = *(const float4*)&sA[c][ty*4+64];
            float4 b0 = *(const float4*)&sB[c][tx*4];
            float4 b1 = *(const float4*)&sB[c][tx*4+64];
            float av[8] = {a0.x,a0.y,a0.z,a0.w,a1.x,a1.y,a1.z,a1.w};
            float bv[8] = {b0.x,b0.y,b0.z,b0.w,b1.x,b1.y,b1.z,b1.w};
            #pragma unroll
            for (int i = 0; i < 8; i++)
                #pragma unroll
                for (int j = 0; j < 8; j++) acc[i][j] += av[i]*bv[j];
        }
    }

    float cnv[8];
    #pragma unroll
    for (int j = 0; j < 8; j++) cnv[j] = nn[c0 + ((j>>2)<<6) + tx*4 + (j&3)];
    #pragma unroll
    for (int i = 0; i < 8; i++){
        int gr = r0 + ((i>>2)<<6) + ty*4 + (i&3);
        float rn = nn[gr];
        float4 o0, o1;
        o0.x = epi(acc[i][0], rn, cnv[0]);
        o0.y = epi(acc[i][1], rn, cnv[1]);
        o0.z = epi(acc[i][2], rn, cnv[2]);
        o0.w = epi(acc[i][3], rn, cnv[3]);
        o1.x = epi(acc[i][4], rn, cnv[4]);
        o1.y = epi(acc[i][5], rn, cnv[5]);
        o1.z = epi(acc[i][6], rn, cnv[6]);
        o1.w = epi(acc[i][7], rn, cnv[7]);
        *(float4*)&pair[(size_t)gr*NPTS + c0 + tx*4]      = o0;
        *(float4*)&pair[(size_t)gr*NPTS + c0 + 64 + tx*4] = o1;
    }

    if (bi != bj){
        #pragma unroll
        for (int h = 0; h < 2; h++){
            __syncthreads();
            #pragma unroll
            for (int i = 0; i < 8; i++){
                int lr = ((i>>2)<<6) + ty*4 + (i&3);
                #pragma unroll
                for (int q = 0; q < 4; q++)
                    sM[tx*4+q][lr] = acc[i][4*h+q];
            }
            __syncthreads();
            for (int i = t; i < 64*128; i += 256){
                int a = i >> 7, col = i & 127;
                int gr = c0 + h*64 + a;
                pair[(size_t)gr*NPTS + r0 + col] = epi(sM[a][col], nn[gr], nn[r0+col]);
            }
        }
    }
}

// ---------------- radix digit finder (descending bins), warp 0 ----------------
__device__ __forceinline__ void find_digit(unsigned* hist, unsigned remk, unsigned* sc)
{
    int t = threadIdx.x, lane = t & 31;
    if (t < 32){
        int base = 255 - 8*lane;
        unsigned bl[8]; unsigned ssum = 0;
        #pragma unroll
        for (int q = 0; q < 8; q++){ bl[q] = hist[base - q]; ssum += bl[q]; }
        unsigned cum = ssum;
        #pragma unroll
        for (int o = 1; o < 32; o <<= 1){
            unsigned vv = __shfl_up_sync(0xffffffffu, cum, o);
            if (lane >= o) cum += vv;
        }
        unsigned before = cum - ssum;
        if (before < remk && remk <= cum){
            unsigned c2 = before; int dig = base; unsigned r2 = 1; bool fnd = false;
            #pragma unroll
            for (int q = 0; q < 8; q++){
                if (!fnd && c2 + bl[q] >= remk){ dig = base - q; r2 = remk - c2; fnd = true; }
                c2 += bl[q];
            }
            sc[0] = (unsigned)dig; sc[1] = r2;
        }
    }
}

// ---------------- select core v3: exact top-20 of vals[0..4095].
//                  v1 structure; pass-1 histogram uses warp-aggregated atomics.
//                  key = (ordval<<32)|(4095-idx): value desc, index asc (jax top_k) ----------------
__device__ __forceinline__ void top20_select(
    unsigned* vals, unsigned* hist,
    unsigned long long* gtlist, unsigned* eqlow, unsigned* sc, int* out)
{
    int t = threadIdx.x, lane = t & 31;
    if (t == 0){ sc[2] = 0; sc[3] = 0; }
    hist[t] = 0;
    __syncthreads();

    // pass 1: top-byte histogram with warp-aggregated atomics
    for (int i = t; i < NPTS; i += 256){
        unsigned bin = vals[i] >> 24;
        unsigned m = __match_any_sync(0xffffffffu, bin);
        if ((m & ((1u << lane) - 1u)) == 0u) atomicAdd(&hist[bin], (unsigned)__popc(m));
    }
    __syncthreads();
    find_digit(hist, KNN, sc);
    __syncthreads();
    unsigned prefix = sc[0] << 24;
    unsigned remk   = sc[1];

    // passes 2..4: only elements matching prefix hit the histogram (low contention)
    #pragma unroll
    for (int d = 2; d >= 0; d--){
        __syncthreads();
        hist[t] = 0;
        __syncthreads();
        int sh = d*8;
        unsigned pmask = 0xFFFFFFFFu << (sh + 8);
        for (int i = t; i < NPTS; i += 256){
            unsigned v = vals[i];
            if ((v & pmask) == prefix) atomicAdd(&hist[(v >> sh) & 255u], 1u);
        }
        __syncthreads();
        find_digit(hist, remk, sc);
        __syncthreads();
        prefix |= sc[0] << sh;
        remk = sc[1];
    }
    unsigned thresh = prefix;

    // collect: strictly-greater keys + equal-valued tie indices
    for (int i = t; i < NPTS; i += 256){
        unsigned v = vals[i];
        if (v > thresh){
            unsigned p = atomicAdd(&sc[2], 1u);
            if (p < 32) gtlist[p] = ((unsigned long long)v << 32) | (unsigned)(NPTS - 1 - i);
        } else if (v == thresh){
            unsigned p = atomicAdd(&sc[3], 1u);
            if (p < 64) eqlow[p] = (unsigned)(NPTS - 1 - i);
        }
    }
    __syncthreads();

    // warp 0 emits the 20 results in (value desc, index asc) order
    if (t < 32){
        unsigned cgt = sc[2];
        unsigned ceq = sc[3] < 64u ? sc[3] : 64u;
        unsigned tot = cgt + ceq;
        unsigned long long tk = (unsigned long long)thresh << 32;
        unsigned long long k0 = 0ull, k1 = 0ull;
        if ((unsigned)lane < tot)
            k0 = ((unsigned)lane < cgt) ? gtlist[lane] : (tk | eqlow[lane - cgt]);
        if ((unsigned)(lane + 32) < tot)
            k1 = tk | eqlow[lane + 32 - cgt];
        for (int it = 0; it < KNN; it++){
            unsigned long long r = (k0 > k1) ? k0 : k1;
            #pragma unroll
            for (int o = 16; o; o >>= 1){
                unsigned long long other = __shfl_xor_sync(0xffffffffu, r, o);
                if (other > r) r = other;
            }
            if (k0 == r) k0 = 0ull;
            else if (k1 == r) k1 = 0ull;
            if (lane == 0) out[it] = (NPTS - 1) - (int)(r & 0xFFFFFFFFu);
        }
    }
}

// ---------------- feature top-k: block per (row, batch) over g_pair ----------------
__global__ void k_topk(void)
{
    __shared__ __align__(16) unsigned int vals[NPTS];
    __shared__ unsigned int hist[256];
    __shared__ unsigned long long gtlist[32];
    __shared__ unsigned int eqlow[64];
    __shared__ unsigned int sc[8];

    int t = threadIdx.x;
    int row = blockIdx.x, b = blockIdx.y;
    const float4* pr = (const float4*)(g_pair + (size_t)b*NPTS*NPTS + (size_t)row*NPTS);
    for (int j = t; j < NPTS/4; j += 256){
        float4 v = __ldg(&pr[j]);
        uint4 o; o.x = f2ord(v.x); o.y = f2ord(v.y); o.z = f2ord(v.z); o.w = f2ord(v.w);
        *(uint4*)&vals[4*j] = o;
    }
    int* out = g_idx1 + ((size_t)b*NPTS + row)*KNN;
    top20_select(vals, hist, gtlist, eqlow, sc, out);
}

// ---------------- coordinate KNN, fused distance + select ----------------
__global__ void k_knn3(const float* __restrict__ x)
{
    __shared__ __align__(16) unsigned int vals[NPTS];
    __shared__ unsigned int hist[256];
    __shared__ unsigned long long gtlist[32];
    __shared__ unsigned int eqlow[64];
    __shared__ unsigned int sc[8];

    int t = threadIdx.x;
    int row = blockIdx.x, b = blockIdx.y;
    const float* xb = x + (size_t)b*NPTS*3;
    const float* nn = g_nx + b*NPTS;
    float xr0 = xb[row*3+0], xr1 = xb[row*3+1], xr2 = xb[row*3+2];
    float rn = nn[row];
    for (int i = t; i < NPTS; i += 256){
        float m0 = __ldg(&xb[i*3+0]), m1 = __ldg(&xb[i*3+1]), m2 = __ldg(&xb[i*3+2]);
        float s = 0.f;
        s = fmaf(xr0, m0, s); s = fmaf(xr1, m1, s); s = fmaf(xr2, m2, s);
        vals[i] = f2ord(epi(s, rn, nn[i]));
    }
    int* out = g_idx2 + ((size_t)b*NPTS + row)*KNN;
    top20_select(vals, hist, gtlist, eqlow, sc, out);
}

// ---------------- dg precompute: a = (Wc-Wd)@h, u = Wd@h; 8 groups per block ----------------
__global__ void k_dgpre(const float* __restrict__ wdg1)
{
    __shared__ float wct[64*64], wdt[64*64];
    __shared__ float hs[4][64];
    int t = threadIdx.x;
    for (int i = t; i < 4096; i += 256){
        int c = i>>6, k = i&63;
        float wc = wdg1[c*128 + k], wd = wdg1[c*128 + 64 + k];
        wdt[k*64+c] = wd;
        wct[k*64+c] = wc - wd;
    }
    __syncthreads();
    int lp = t>>6, c = t&63;
    float wa[64], wu[64];
    #pragma unroll
    for (int k = 0; k < 64; k++){ wa[k] = wct[k*64+c]; wu[k] = wdt[k*64+c]; }
    for (int g2 = 0; g2 < 8; g2++){
        int p = (blockIdx.x*8 + g2)*4 + lp;
        __syncthreads();
        hs[lp][c] = g_h[p*64+c];
        __syncthreads();
        float sa = 0.f, su = 0.f;
        #pragma unroll
        for (int k = 0; k < 64; k++){ float h = hs[lp][k]; sa += wa[k]*h; su += wu[k]*h; }
        g_a[p*64+c] = sa;
        g_u[p*64+c] = su;
    }
}

// ---------------- dg edge conv: 8 points/block, warp = point, 2 channels/thread.
//                  Each t1 float4 is reused for 8 FMA (2 channels x 4 k) -> FMA-pipe bound ----------------
__global__ void __launch_bounds__(256) k_dgedge(
    const float* __restrict__ w2,
    const float* __restrict__ g1v, const float* __restrict__ b1v,
    const float* __restrict__ g2v, const float* __restrict__ b2v)
{
    __shared__ float wt[4096];              // [k][c] transposed, 16KB
    __shared__ float t1s[8][KNN][64];       // 40KB
    __shared__ float sg1[64], sb1[64], sg2[64], sb2[64];
    int t = threadIdx.x;
    for (int i = t; i < 4096; i += 256){ int c = i>>6, k = i&63; wt[k*64+c] = w2[i]; }
    if (t < 64){ sg1[t] = g1v[t]; sb1[t] = b1v[t]; sg2[t] = g2v[t]; sb2[t] = b2v[t]; }
    __syncthreads();

    int p0   = blockIdx.x*8;
    int base = (p0 >> 12) * NPTS;

    // phase 1: build all 8x20 t1 vectors
    for (int i = t; i < 8*KNN*64; i += 256){
        int pt = i / (KNN*64);
        int r  = i - pt*(KNN*64);
        int j  = r >> 6, c = r & 63;
        int p  = p0 + pt;
        int m  = g_idx1[p*KNN + j];
        float v = (g_a[p*64+c] + g_u[(base+m)*64 + c]) * sg1[c] + sb1[c];
        t1s[pt][j][c] = lrelu(v);
    }

    // phase 2: warp = point, lane = channel pair
    int cp = t & 31, pt = t >> 5;
    int c0 = 2*cp, c1 = 2*cp + 1;
    float wr0[64], wr1[64];
    #pragma unroll
    for (int k = 0; k < 64; k++){ wr0[k] = wt[k*64 + c0]; wr1[k] = wt[k*64 + c1]; }
    float G20 = sg2[c0], B20 = sb2[c0];
    float G21 = sg2[c1], B21 = sb2[c1];
    __syncthreads();

    float mx0 = -3.4e38f, mx1 = -3.4e38f;
    for (int j = 0; j < KNN; j++){
        const float4* tp4 = (const float4*)t1s[pt][j];
        float s0 = 0.f, s1 = 0.f;
        #pragma unroll
        for (int k4 = 0; k4 < 16; k4++){
            float4 hv = tp4[k4];
            s0 += wr0[4*k4+0]*hv.x + wr0[4*k4+1]*hv.y + wr0[4*k4+2]*hv.z + wr0[4*k4+3]*hv.w;
            s1 += wr1[4*k4+0]*hv.x + wr1[4*k4+1]*hv.y + wr1[4*k4+2]*hv.z + wr1[4*k4+3]*hv.w;
        }
        mx0 = fmaxf(mx0, lrelu(s0*G20 + B20));
        mx1 = fmaxf(mx1, lrelu(s1*G21 + B21));
    }
    *(float2*)&g_hdg[(size_t)(p0+pt)*64 + c0] = make_float2(mx0, mx1);
}

// ---------------- sn branch: gather-max of per-point MLP output ----------------
__global__ void k_snmax()
{
    int t = threadIdx.x;
    int lp = t>>6, c = t&63;
    int p    = blockIdx.x*4 + lp;
    int base = (p >> 12) * NPTS;
    const int* ip = &g_idx2[p*KNN];
    float mx = -3.4e38f;
    for (int j = 0; j < KNN; j++){
        int m = ip[j];
        mx = fmaxf(mx, g_p2[(base+m)*64 + c]);
    }
    g_hsn[p*64+c] = mx;
}

// ---------------- conv5 GEMM: 128x128 tiles, 8x8 per thread, K=128 in 4 chunks ----------------
__global__ void __launch_bounds__(256, 2) k_conv5(
    const float* __restrict__ w5, const float* __restrict__ g5,
    const float* __restrict__ b5, float* __restrict__ out)
{
    __shared__ float sBuf[2*32*132];
    float (*sW)[132] = (float(*)[132])sBuf;
    float (*sH)[132] = (float(*)[132])(sBuf + 32*132);
    int t   = threadIdx.x;
    int co0 = blockIdx.y*128;
    int pt0 = blockIdx.x*128;
    int ty = t >> 4, tx = t & 15;
    float acc[8][8];
    #pragma unroll
    for (int i = 0; i < 8; i++)
        #pragma unroll
        for (int j = 0; j < 8; j++) acc[i][j] = 0.f;

    for (int kc = 0; kc < 4; kc++){
        __syncthreads();
        for (int i = t; i < 128*32; i += 256){
            int r = i >> 5, c = i & 31;
            sW[c][r] = w5[(co0+r)*128 + kc*32 + c];
        }
        for (int i = t; i < 128*32; i += 256){
            int r = i >> 5, c = i & 31;
            sH[c][r] = g_h4[(size_t)(pt0+r)*128 + kc*32 + c];
        }
        __syncthreads();
        #pragma unroll
        for (int c = 0; c < 32; c++){
            float4 a0 = *(const float4*)&sW[c][ty*4];
            float4 a1 = *(const float4*)&sW[c][ty*4+64];
            float4 b0 = *(const float4*)&sH[c][tx*4];
            float4 b1 = *(const float4*)&sH[c][tx*4+64];
            float av[8] = {a0.x,a0.y,a0.z,a0.w,a1.x,a1.y,a1.z,a1.w};
            float bv[8] = {b0.x,b0.y,b0.z,b0.w,b1.x,b1.y,b1.z,b1.w};
            #pragma unroll
            for (int i = 0; i < 8; i++)
                #pragma unroll
                for (int j = 0; j < 8; j++) acc[i][j] += av[i]*bv[j];
        }
    }

    int bI = pt0 >> 12;
    int n00 = (pt0 & (NPTS-1)) + tx*4;
    #pragma unroll
    for (int i = 0; i < 8; i++){
        int co = co0 + ((i>>2)<<6) + ty*4 + (i&3);
        float G = g5[co], Bv = b5[co];
        float4 o0, o1;
        o0.x = lrelu(acc[i][0]*G + Bv);
        o0.y = lrelu(acc[i][1]*G + Bv);
        o0.z = lrelu(acc[i][2]*G + Bv);
        o0.w = lrelu(acc[i][3]*G + Bv);
        o1.x = lrelu(acc[i][4]*G + Bv);
        o1.y = lrelu(acc[i][5]*G + Bv);
        o1.z = lrelu(acc[i][6]*G + Bv);
        o1.w = lrelu(acc[i][7]*G + Bv);
        *(float4*)&out[((size_t)bI*512 + co)*NPTS + n00]      = o0;
        *(float4*)&out[((size_t)bI*512 + co)*NPTS + n00 + 64] = o1;
    }
}

// ---------------- launch ----------------
extern "C" void kernel_launch(void* const* d_in, const int* in_sizes, int n_in,
                              void* d_out, int out_size)
{
    const float* x    = (const float*)d_in[0];
    const float* w1   = (const float*)d_in[1];
    const float* g1   = (const float*)d_in[2];
    const float* b1   = (const float*)d_in[3];
    const float* w2   = (const float*)d_in[4];
    const float* g2   = (const float*)d_in[5];
    const float* b2   = (const float*)d_in[6];
    const float* wdg1 = (const float*)d_in[7];
    const float* gdg1 = (const float*)d_in[8];
    const float* bdg1 = (const float*)d_in[9];
    const float* wdg2 = (const float*)d_in[10];
    const float* gdg2 = (const float*)d_in[11];
    const float* bdg2 = (const float*)d_in[12];
    const float* wsn1 = (const float*)d_in[13];
    const float* gsn1 = (const float*)d_in[14];
    const float* bsn1 = (const float*)d_in[15];
    const float* wsn2 = (const float*)d_in[16];
    const float* gsn2 = (const float*)d_in[17];
    const float* bsn2 = (const float*)d_in[18];
    const float* w3   = (const float*)d_in[19];
    const float* g3   = (const float*)d_in[20];
    const float* b3   = (const float*)d_in[21];
    const float* w4   = (const float*)d_in[22];
    const float* g4   = (const float*)d_in[23];
    const float* b4   = (const float*)d_in[24];
    const float* w5   = (const float*)d_in[25];
    const float* g5   = (const float*)d_in[26];
    const float* b5   = (const float*)d_in[27];

    float* out  = (float*)d_out;

    // conv1 + conv2 (in-place) + norms
    k_conv1    <<<TOTPTS/4,  256>>>(x, w1, g1, b1);
    k_pconv<64><<<TOTPTS/32, 256>>>(0, w2, g2, b2);
    k_norms    <<<TOTPTS/256,256>>>(x);

    const int NTILE = 32*33/2;   // 528 upper-triangular 128x128 tiles
    // feature KNN (all batches, single launches)
    k_pair<<<dim3(NTILE, BB), 256>>>();
    k_topk<<<dim3(NPTS,  BB), 256>>>();
    // coordinate KNN (fused distance + select)
    k_knn3<<<dim3(NPTS,  BB), 256>>>(x);

    // dg branch
    k_dgpre <<<TOTPTS/32, 256>>>(wdg1);
    k_dgedge<<<TOTPTS/8,  256>>>(wdg2, gdg1, bdg1, gdg2, bdg2);

    // sn branch: per-point MLP then gather-max
    k_pconv<64><<<TOTPTS/32, 256>>>(1, wsn1, gsn1, bsn1);
    k_pconv<64><<<TOTPTS/32, 256>>>(2, wsn2, gsn2, bsn2);
    k_snmax    <<<TOTPTS/4,  256>>>();

    // head
    k_pconv<64> <<<TOTPTS/32, 256>>>(3, w3, g3, b3);
    k_pconv<128><<<TOTPTS/16, 256>>>(4, w4, g4, b4);
    k_conv5     <<<dim3(TOTPTS/128, 4), 256>>>(w5, g5, b5, out);
}

// round 11
// speedup vs baseline: 1.0976x; 1.0976x over previous
#include <cuda_runtime.h>

#define BB    8
#define NPTS  4096
#define KNN   20
#define TOTPTS (BB*NPTS)

// ---------------- static device scratch (sanctioned workaround) ----------------
static __device__ float g_pair[(size_t)BB*NPTS*NPTS]; // 512MB: all 8 batches' pair matrices
static __device__ float g_h  [TOTPTS*64];   // features after conv1+conv2, (B,N,64)
static __device__ float g_nh [TOTPTS];      // ||h||^2
static __device__ float g_nx [TOTPTS];      // ||x||^2
static __device__ int   g_idx1[TOTPTS*KNN];
static __device__ int   g_idx2[TOTPTS*KNN];
static __device__ float g_a  [TOTPTS*64];   // (Wc-Wd)@h
static __device__ float g_u  [TOTPTS*64];   // Wd@h
static __device__ float g_hdg[TOTPTS*64];   // after dg branch max
static __device__ float g_p2 [TOTPTS*64];   // sn-branch per-point MLP output
static __device__ float g_hsn[TOTPTS*64];   // after sn gather-max (then conv3 in-place)
static __device__ float g_h4 [TOTPTS*128];  // after conv4

__device__ __forceinline__ float lrelu(float v){ return fmaxf(v, 0.01f*v); }

// reference-order epilogue (identical codegen at every use site)
__device__ __forceinline__ float epi(float acc, float rn, float cn){
    return 2.f*acc - rn - cn;
}

__device__ __forceinline__ unsigned f2ord(float f){
    unsigned u = __float_as_uint(f);
    return (u & 0x80000000u) ? ~u : (u | 0x80000000u);
}

__device__ __forceinline__ const float* pconv_in(int sel){
    switch(sel){ case 0: return g_h; case 1: return g_hdg; case 2: return g_p2;
                 case 3: return g_hsn; default: return g_hsn; }
}
__device__ __forceinline__ float* pconv_out(int sel){
    switch(sel){ case 0: return g_h; case 1: return g_p2; case 2: return g_p2;
                 case 3: return g_hsn; default: return g_h4; }
}

// ---------------- conv1: x(B,N,3) -> g_h (64ch) ----------------
__global__ void k_conv1(const float* __restrict__ x, const float* __restrict__ w,
                        const float* __restrict__ g, const float* __restrict__ b)
{
    __shared__ float sw[192], sg[64], sb[64];
    int t = threadIdx.x;
    if (t < 192) sw[t] = w[t];
    if (t < 64){ sg[t] = g[t]; sb[t] = b[t]; }
    __syncthreads();
    int lp = t >> 6, c = t & 63;
    int p  = blockIdx.x*4 + lp;
    float x0 = x[p*3+0], x1 = x[p*3+1], x2 = x[p*3+2];
    float v = sw[c*3+0]*x0 + sw[c*3+1]*x1 + sw[c*3+2]*x2;
    g_h[p*64+c] = lrelu(v*sg[c] + sb[c]);
}

// ---------------- pointwise conv 64 -> COUT with BN+LReLU; 8 point-groups per block ----------------
template<int COUT>
__global__ void k_pconv(int sel, const float* __restrict__ w,
                        const float* __restrict__ g, const float* __restrict__ b)
{
    const int PPB = 256/COUT;
    const int GRP = 8;
    __shared__ float wt[64*COUT];
    __shared__ float hs[PPB][64];
    __shared__ float sg[COUT], sb[COUT];
    const float* in  = pconv_in(sel);
    float*       out = pconv_out(sel);
    int t = threadIdx.x;
    for (int i = t; i < 64*COUT; i += 256){ int c = i>>6, k = i&63; wt[k*COUT+c] = w[i]; }
    for (int i = t; i < COUT;    i += 256){ sg[i] = g[i]; sb[i] = b[i]; }
    __syncthreads();
    int lp = t / COUT, c = t % COUT;
    float wr[64];
    #pragma unroll
    for (int k = 0; k < 64; k++) wr[k] = wt[k*COUT+c];
    float G = sg[c], Bv = sb[c];
    for (int g2 = 0; g2 < GRP; g2++){
        int p = (blockIdx.x*GRP + g2)*PPB + lp;
        __syncthreads();
        if (c < 64) hs[lp][c] = in[p*64+c];
        __syncthreads();
        float s = 0.f;
        #pragma unroll
        for (int k = 0; k < 64; k++) s += wr[k]*hs[lp][k];
        out[p*COUT+c] = lrelu(s*G + Bv);
    }
}

// ---------------- squared norms ----------------
__global__ void k_norms(const float* __restrict__ x)
{
    int p = blockIdx.x*256 + threadIdx.x;
    const float* hp = &g_h[p*64];
    float s = 0.f;
    #pragma unroll
    for (int k = 0; k < 64; k++){ float v = hp[k]; s += v*v; }
    g_nh[p] = s;
    float x0 = x[p*3], x1 = x[p*3+1], x2 = x[p*3+2];
    float sx = 0.f;
    sx = fmaf(x0,x0,sx); sx = fmaf(x1,x1,sx); sx = fmaf(x2,x2,sx);
    g_nx[p] = sx;
}

// ---------------- feature pair matrix: 128x128 tiles, 8x8 per thread,
//                  triangular over 32x32 tile grid; mirror via raw-dot smem staging ----------------
__global__ void __launch_bounds__(256, 2) k_pair(void)
{
    __shared__ float sBuf[2*32*132];
    float (*sA)[132] = (float(*)[132])sBuf;
    float (*sB)[132] = (float(*)[132])(sBuf + 32*132);
    float (*sM)[132] = (float(*)[132])sBuf;   // mirror staging alias (64 rows x 128 cols)

    int b = blockIdx.y;
    const float* A  = g_h + (size_t)b*NPTS*64;
    const float* nn = g_nh + b*NPTS;
    float* pair = g_pair + (size_t)b*NPTS*NPTS;
    int t = threadIdx.x;

    int u = blockIdx.x;
    int bi = 0, rem = 32;
    while (u >= rem){ u -= rem; rem--; bi++; }
    int bj = bi + u;
    int r0 = bi*128, c0 = bj*128;

    int ty = t >> 4, tx = t & 15;
    float acc[8][8];
    #pragma unroll
    for (int i = 0; i < 8; i++)
        #pragma unroll
        for (int j = 0; j < 8; j++) acc[i][j] = 0.f;

    for (int kc = 0; kc < 2; kc++){
        __syncthreads();
        for (int i = t; i < 128*32; i += 256){
            int r = i >> 5, c = i & 31;
            sA[c][r] = A[(size_t)(r0+r)*64 + kc*32 + c];
        }
        for (int i = t; i < 128*32; i += 256){
            int r = i >> 5, c = i & 31;
            sB[c][r] = A[(size_t)(c0+r)*64 + kc*32 + c];
        }
        __syncthreads();
        #pragma unroll
        for (int c = 0; c < 32; c++){
            float4 a0 = *(const float4*)&sA[c][ty*4];
            float4 a1 = *(const float4*)&sA[c][ty*4+64];
            float4 b0 = *(const float4*)&sB[c][tx*4];
            float4 b1 = *(const float4*)&sB[c][tx*4+64];
            float av[8] = {a0.x,a0.y,a0.z,a0.w,a1.x,a1.y,a1.z,a1.w};
            float bv[8] = {b0.x,b0.y,b0.z,b0.w,b1.x,b1.y,b1.z,b1.w};
            #pragma unroll
            for (int i = 0; i < 8; i++)
                #pragma unroll
                for (int j = 0; j < 8; j++) acc[i][j] += av[i]*bv[j];
        }
    }

    float cnv[8];
    #pragma unroll
    for (int j = 0; j < 8; j++) cnv[j] = nn[c0 + ((j>>2)<<6) + tx*4 + (j&3)];
    #pragma unroll
    for (int i = 0; i < 8; i++){
        int gr = r0 + ((i>>2)<<6) + ty*4 + (i&3);
        float rn = nn[gr];
        float4 o0, o1;
        o0.x = epi(acc[i][0], rn, cnv[0]);
        o0.y = epi(acc[i][1], rn, cnv[1]);
        o0.z = epi(acc[i][2], rn, cnv[2]);
        o0.w = epi(acc[i][3], rn, cnv[3]);
        o1.x = epi(acc[i][4], rn, cnv[4]);
        o1.y = epi(acc[i][5], rn, cnv[5]);
        o1.z = epi(acc[i][6], rn, cnv[6]);
        o1.w = epi(acc[i][7], rn, cnv[7]);
        *(float4*)&pair[(size_t)gr*NPTS + c0 + tx*4]      = o0;
        *(float4*)&pair[(size_t)gr*NPTS + c0 + 64 + tx*4] = o1;
    }

    if (bi != bj){
        #pragma unroll
        for (int h = 0; h < 2; h++){
            __syncthreads();
            #pragma unroll
            for (int i = 0; i < 8; i++){
                int lr = ((i>>2)<<6) + ty*4 + (i&3);
                #pragma unroll
                for (int q = 0; q < 4; q++)
                    sM[tx*4+q][lr] = acc[i][4*h+q];
            }
            __syncthreads();
            for (int i = t; i < 64*128; i += 256){
                int a = i >> 7, col = i & 127;
                int gr = c0 + h*64 + a;
                pair[(size_t)gr*NPTS + r0 + col] = epi(sM[a][col], nn[gr], nn[r0+col]);
            }
        }
    }
}

// ---------------- radix digit finder (descending bins), warp 0 ----------------
__device__ __forceinline__ void find_digit(unsigned* hist, unsigned remk, unsigned* sc)
{
    int t = threadIdx.x, lane = t & 31;
    if (t < 32){
        int base = 255 - 8*lane;
        unsigned bl[8]; unsigned ssum = 0;
        #pragma unroll
        for (int q = 0; q < 8; q++){ bl[q] = hist[base - q]; ssum += bl[q]; }
        unsigned cum = ssum;
        #pragma unroll
        for (int o = 1; o < 32; o <<= 1){
            unsigned vv = __shfl_up_sync(0xffffffffu, cum, o);
            if (lane >= o) cum += vv;
        }
        unsigned before = cum - ssum;
        if (before < remk && remk <= cum){
            unsigned c2 = before; int dig = base; unsigned r2 = 1; bool fnd = false;
            #pragma unroll
            for (int q = 0; q < 8; q++){
                if (!fnd && c2 + bl[q] >= remk){ dig = base - q; r2 = remk - c2; fnd = true; }
                c2 += bl[q];
            }
            sc[0] = (unsigned)dig; sc[1] = r2;
        }
    }
}

// ---------------- warp-aggregated histogram add for one ordered value ----------------
__device__ __forceinline__ void hist_add(unsigned* hist, unsigned v, int lane)
{
    unsigned bin = v >> 24;
    unsigned m = __match_any_sync(0xffffffffu, bin);
    if ((m & ((1u << lane) - 1u)) == 0u) atomicAdd(&hist[bin], (unsigned)__popc(m));
}

// ---------------- select rest: pass-1 histogram ALREADY populated by caller.
//                  exact top-20; key = (ordval<<32)|(4095-idx): value desc, index asc ----------------
__device__ __forceinline__ void top20_select_posthist(
    unsigned* vals, unsigned* hist,
    unsigned long long* gtlist, unsigned* eqlow, unsigned* sc, int* out)
{
    int t = threadIdx.x, lane = t & 31;
    __syncthreads();
    find_digit(hist, KNN, sc);
    __syncthreads();
    unsigned prefix = sc[0] << 24;
    unsigned remk   = sc[1];

    // passes 2..4: only elements matching prefix hit the histogram (low contention)
    #pragma unroll
    for (int d = 2; d >= 0; d--){
        __syncthreads();
        hist[t] = 0;
        __syncthreads();
        int sh = d*8;
        unsigned pmask = 0xFFFFFFFFu << (sh + 8);
        for (int i = t; i < NPTS; i += 256){
            unsigned v = vals[i];
            if ((v & pmask) == prefix) atomicAdd(&hist[(v >> sh) & 255u], 1u);
        }
        __syncthreads();
        find_digit(hist, remk, sc);
        __syncthreads();
        prefix |= sc[0] << sh;
        remk = sc[1];
    }
    unsigned thresh = prefix;

    // collect: strictly-greater keys + equal-valued tie indices
    for (int i = t; i < NPTS; i += 256){
        unsigned v = vals[i];
        if (v > thresh){
            unsigned p = atomicAdd(&sc[2], 1u);
            if (p < 32) gtlist[p] = ((unsigned long long)v << 32) | (unsigned)(NPTS - 1 - i);
        } else if (v == thresh){
            unsigned p = atomicAdd(&sc[3], 1u);
            if (p < 64) eqlow[p] = (unsigned)(NPTS - 1 - i);
        }
    }
    __syncthreads();

    // warp 0 emits the 20 results in (value desc, index asc) order
    if (t < 32){
        unsigned cgt = sc[2];
        unsigned ceq = sc[3] < 64u ? sc[3] : 64u;
        unsigned tot = cgt + ceq;
        unsigned long long tk = (unsigned long long)thresh << 32;
        unsigned long long k0 = 0ull, k1 = 0ull;
        if ((unsigned)lane < tot)
            k0 = ((unsigned)lane < cgt) ? gtlist[lane] : (tk | eqlow[lane - cgt]);
        if ((unsigned)(lane + 32) < tot)
            k1 = tk | eqlow[lane + 32 - cgt];
        for (int it = 0; it < KNN; it++){
            unsigned long long r = (k0 > k1) ? k0 : k1;
            #pragma unroll
            for (int o = 16; o; o >>= 1){
                unsigned long long other = __shfl_xor_sync(0xffffffffu, r, o);
                if (other > r) r = other;
            }
            if (k0 == r) k0 = 0ull;
            else if (k1 == r) k1 = 0ull;
            if (lane == 0) out[it] = (NPTS - 1) - (int)(r & 0xFFFFFFFFu);
        }
    }
}

// ---------------- feature top-k: block per (row, batch); pass-1 fused into load ----------------
__global__ void k_topk(void)
{
    __shared__ __align__(16) unsigned int vals[NPTS];
    __shared__ unsigned int hist[256];
    __shared__ unsigned long long gtlist[32];
    __shared__ unsigned int eqlow[64];
    __shared__ unsigned int sc[8];

    int t = threadIdx.x, lane = t & 31;
    int row = blockIdx.x, b = blockIdx.y;
    hist[t] = 0;
    if (t == 0){ sc[2] = 0; sc[3] = 0; }
    __syncthreads();

    const float4* pr = (const float4*)(g_pair + (size_t)b*NPTS*NPTS + (size_t)row*NPTS);
    for (int j = t; j < NPTS/4; j += 256){
        float4 v = __ldg(&pr[j]);
        uint4 o; o.x = f2ord(v.x); o.y = f2ord(v.y); o.z = f2ord(v.z); o.w = f2ord(v.w);
        *(uint4*)&vals[4*j] = o;
        hist_add(hist, o.x, lane);
        hist_add(hist, o.y, lane);
        hist_add(hist, o.z, lane);
        hist_add(hist, o.w, lane);
    }
    int* out = g_idx1 + ((size_t)b*NPTS + row)*KNN;
    top20_select_posthist(vals, hist, gtlist, eqlow, sc, out);
}

// ---------------- coordinate KNN, fused distance + select; pass-1 fused into compute ----------------
__global__ void k_knn3(const float* __restrict__ x)
{
    __shared__ __align__(16) unsigned int vals[NPTS];
    __shared__ unsigned int hist[256];
    __shared__ unsigned long long gtlist[32];
    __shared__ unsigned int eqlow[64];
    __shared__ unsigned int sc[8];

    int t = threadIdx.x, lane = t & 31;
    int row = blockIdx.x, b = blockIdx.y;
    hist[t] = 0;
    if (t == 0){ sc[2] = 0; sc[3] = 0; }
    __syncthreads();

    const float* xb = x + (size_t)b*NPTS*3;
    const float* nn = g_nx + b*NPTS;
    float xr0 = xb[row*3+0], xr1 = xb[row*3+1], xr2 = xb[row*3+2];
    float rn = nn[row];
    for (int i = t; i < NPTS; i += 256){
        float m0 = __ldg(&xb[i*3+0]), m1 = __ldg(&xb[i*3+1]), m2 = __ldg(&xb[i*3+2]);
        float s = 0.f;
        s = fmaf(xr0, m0, s); s = fmaf(xr1, m1, s); s = fmaf(xr2, m2, s);
        unsigned v = f2ord(epi(s, rn, nn[i]));
        vals[i] = v;
        hist_add(hist, v, lane);
    }
    int* out = g_idx2 + ((size_t)b*NPTS + row)*KNN;
    top20_select_posthist(vals, hist, gtlist, eqlow, sc, out);
}

// ---------------- dg precompute: a = (Wc-Wd)@h, u = Wd@h; 8 groups per block ----------------
__global__ void k_dgpre(const float* __restrict__ wdg1)
{
    __shared__ float wct[64*64], wdt[64*64];
    __shared__ float hs[4][64];
    int t = threadIdx.x;
    for (int i = t; i < 4096; i += 256){
        int c = i>>6, k = i&63;
        float wc = wdg1[c*128 + k], wd = wdg1[c*128 + 64 + k];
        wdt[k*64+c] = wd;
        wct[k*64+c] = wc - wd;
    }
    __syncthreads();
    int lp = t>>6, c = t&63;
    float wa[64], wu[64];
    #pragma unroll
    for (int k = 0; k < 64; k++){ wa[k] = wct[k*64+c]; wu[k] = wdt[k*64+c]; }
    for (int g2 = 0; g2 < 8; g2++){
        int p = (blockIdx.x*8 + g2)*4 + lp;
        __syncthreads();
        hs[lp][c] = g_h[p*64+c];
        __syncthreads();
        float sa = 0.f, su = 0.f;
        #pragma unroll
        for (int k = 0; k < 64; k++){ float h = hs[lp][k]; sa += wa[k]*h; su += wu[k]*h; }
        g_a[p*64+c] = sa;
        g_u[p*64+c] = su;
    }
}

// ---------------- dg edge conv, two-phase (R8 version: 4 pts/block, 1 ch/thread) ----------------
__global__ void k_dgedge(const float* __restrict__ w2,
                         const float* __restrict__ g1v, const float* __restrict__ b1v,
                         const float* __restrict__ g2v, const float* __restrict__ b2v)
{
    __shared__ float wt[4096];
    __shared__ float t1s[4][KNN][64];
    __shared__ float sg1[64], sb1[64], sg2[64], sb2[64];
    int t = threadIdx.x;
    for (int i = t; i < 4096; i += 256){ int c = i>>6, k = i&63; wt[k*64+c] = w2[i]; }
    if (t < 64){ sg1[t] = g1v[t]; sb1[t] = b1v[t]; sg2[t] = g2v[t]; sb2[t] = b2v[t]; }
    __syncthreads();
    int lp = t>>6, c = t&63;
    int p    = blockIdx.x*4 + lp;
    int base = (p >> 12) * NPTS;
    float ac = g_a[p*64+c];
    float G1 = sg1[c], B1 = sb1[c], G2 = sg2[c], B2 = sb2[c];
    const int* ip = &g_idx1[p*KNN];
    #pragma unroll 5
    for (int j = 0; j < KNN; j++){
        int m = ip[j];
        float v = (ac + g_u[(base+m)*64 + c]) * G1 + B1;
        t1s[lp][j][c] = lrelu(v);
    }
    float wr[64];
    #pragma unroll
    for (int k = 0; k < 64; k++) wr[k] = wt[k*64+c];
    __syncthreads();
    float mx = -3.4e38f;
    for (int j = 0; j < KNN; j++){
        const float4* tp4 = (const float4*)t1s[lp][j];
        float s = 0.f;
        #pragma unroll
        for (int k4 = 0; k4 < 16; k4++){
            float4 hv = tp4[k4];
            s += wr[4*k4+0]*hv.x + wr[4*k4+1]*hv.y + wr[4*k4+2]*hv.z + wr[4*k4+3]*hv.w;
        }
        s = lrelu(s*G2 + B2);
        mx = fmaxf(mx, s);
    }
    g_hdg[p*64+c] = mx;
}

// ---------------- sn branch: gather-max of per-point MLP output ----------------
__global__ void k_snmax()
{
    int t = threadIdx.x;
    int lp = t>>6, c = t&63;
    int p    = blockIdx.x*4 + lp;
    int base = (p >> 12) * NPTS;
    const int* ip = &g_idx2[p*KNN];
    float mx = -3.4e38f;
    for (int j = 0; j < KNN; j++){
        int m = ip[j];
        mx = fmaxf(mx, g_p2[(base+m)*64 + c]);
    }
    g_hsn[p*64+c] = mx;
}

// ---------------- conv5 GEMM (R8 version: 64x64 tiles, 4x4 per thread) ----------------
__global__ void k_conv5(const float* __restrict__ w5, const float* __restrict__ g5,
                        const float* __restrict__ b5, float* __restrict__ out)
{
    __shared__ float wt[64][68];
    __shared__ float ht[64][68];
    int t   = threadIdx.x;
    int co0 = blockIdx.y*64;
    int pt0 = blockIdx.x*64;
    int tr = (t>>4)<<2, tc = (t&15)<<2;
    float acc[4][4] = {{0.f,0.f,0.f,0.f},{0.f,0.f,0.f,0.f},{0.f,0.f,0.f,0.f},{0.f,0.f,0.f,0.f}};
    for (int kc = 0; kc < 2; kc++){
        __syncthreads();
        for (int i = t; i < 4096; i += 256){ int c = i>>6, k = i&63; wt[k][c] = w5[(co0+c)*128 + kc*64 + k]; }
        for (int i = t; i < 4096; i += 256){ int q = i>>6, k = i&63; ht[k][q] = g_h4[(size_t)(pt0+q)*128 + kc*64 + k]; }
        __syncthreads();
        #pragma unroll
        for (int k = 0; k < 64; k++){
            float4 wv = *(const float4*)&wt[k][tr];
            float4 hv = *(const float4*)&ht[k][tc];
            acc[0][0] += wv.x*hv.x; acc[0][1] += wv.x*hv.y; acc[0][2] += wv.x*hv.z; acc[0][3] += wv.x*hv.w;
            acc[1][0] += wv.y*hv.x; acc[1][1] += wv.y*hv.y; acc[1][2] += wv.y*hv.z; acc[1][3] += wv.y*hv.w;
            acc[2][0] += wv.z*hv.x; acc[2][1] += wv.z*hv.y; acc[2][2] += wv.z*hv.z; acc[2][3] += wv.z*hv.w;
            acc[3][0] += wv.w*hv.x; acc[3][1] += wv.w*hv.y; acc[3][2] += wv.w*hv.z; acc[3][3] += wv.w*hv.w;
        }
    }
    int bI = pt0 >> 12;
    int n0 = (pt0 + tc) & (NPTS-1);
    #pragma unroll
    for (int i = 0; i < 4; i++){
        int co = co0 + tr + i;
        float G = g5[co], Bv = b5[co];
        float4 o;
        o.x = lrelu(acc[i][0]*G + Bv);
        o.y = lrelu(acc[i][1]*G + Bv);
        o.z = lrelu(acc[i][2]*G + Bv);
        o.w = lrelu(acc[i][3]*G + Bv);
        *(float4*)&out[((size_t)bI*512 + co)*NPTS + n0] = o;
    }
}

// ---------------- launch ----------------
extern "C" void kernel_launch(void* const* d_in, const int* in_sizes, int n_in,
                              void* d_out, int out_size)
{
    const float* x    = (const float*)d_in[0];
    const float* w1   = (const float*)d_in[1];
    const float* g1   = (const float*)d_in[2];
    const float* b1   = (const float*)d_in[3];
    const float* w2   = (const float*)d_in[4];
    const float* g2   = (const float*)d_in[5];
    const float* b2   = (const float*)d_in[6];
    const float* wdg1 = (const float*)d_in[7];
    const float* gdg1 = (const float*)d_in[8];
    const float* bdg1 = (const float*)d_in[9];
    const float* wdg2 = (const float*)d_in[10];
    const float* gdg2 = (const float*)d_in[11];
    const float* bdg2 = (const float*)d_in[12];
    const float* wsn1 = (const float*)d_in[13];
    const float* gsn1 = (const float*)d_in[14];
    const float* bsn1 = (const float*)d_in[15];
    const float* wsn2 = (const float*)d_in[16];
    const float* gsn2 = (const float*)d_in[17];
    const float* bsn2 = (const float*)d_in[18];
    const float* w3   = (const float*)d_in[19];
    const float* g3   = (const float*)d_in[20];
    const float* b3   = (const float*)d_in[21];
    const float* w4   = (const float*)d_in[22];
    const float* g4   = (const float*)d_in[23];
    const float* b4   = (const float*)d_in[24];
    const float* w5   = (const float*)d_in[25];
    const float* g5   = (const float*)d_in[26];
    const float* b5   = (const float*)d_in[27];

    float* out  = (float*)d_out;

    // conv1 + conv2 (in-place) + norms
    k_conv1    <<<TOTPTS/4,  256>>>(x, w1, g1, b1);
    k_pconv<64><<<TOTPTS/32, 256>>>(0, w2, g2, b2);
    k_norms    <<<TOTPTS/256,256>>>(x);

    const int NTILE = 32*33/2;   // 528 upper-triangular 128x128 tiles
    // feature KNN (all batches, single launches)
    k_pair<<<dim3(NTILE, BB), 256>>>();
    k_topk<<<dim3(NPTS,  BB), 256>>>();
    // coordinate KNN (fused distance + select)
    k_knn3<<<dim3(NPTS,  BB), 256>>>(x);

    // dg branch
    k_dgpre <<<TOTPTS/32, 256>>>(wdg1);
    k_dgedge<<<TOTPTS/4,  256>>>(wdg2, gdg1, bdg1, gdg2, bdg2);

    // sn branch: per-point MLP then gather-max
    k_pconv<64><<<TOTPTS/32, 256>>>(1, wsn1, gsn1, bsn1);
    k_pconv<64><<<TOTPTS/32, 256>>>(2, wsn2, gsn2, bsn2);
    k_snmax    <<<TOTPTS/4,  256>>>();

    // head
    k_pconv<64> <<<TOTPTS/32, 256>>>(3, w3, g3, b3);
    k_pconv<128><<<TOTPTS/16, 256>>>(4, w4, g4, b4);
    k_conv5     <<<dim3(TOTPTS/64, 512/64), 256>>>(w5, g5, b5, out);
}

// round 12
// speedup vs baseline: 1.1526x; 1.0501x over previous
#include <cuda_runtime.h>

#define BB    8
#define NPTS  4096
#define KNN   20
#define TOTPTS (BB*NPTS)

// ---------------- static device scratch (sanctioned workaround) ----------------
static __device__ float g_pair[(size_t)BB*NPTS*NPTS]; // 512MB: all 8 batches' pair matrices
static __device__ float g_h  [TOTPTS*64];   // features after conv1+conv2, (B,N,64)
static __device__ float g_nh [TOTPTS];      // ||h||^2
static __device__ float g_nx [TOTPTS];      // ||x||^2
static __device__ int   g_idx1[TOTPTS*KNN];
static __device__ int   g_idx2[TOTPTS*KNN];
static __device__ float g_a  [TOTPTS*64];   // (Wc-Wd)@h
static __device__ float g_u  [TOTPTS*64];   // Wd@h
static __device__ float g_hdg[TOTPTS*64];   // after dg branch max
static __device__ float g_p2 [TOTPTS*64];   // sn-branch per-point MLP output
static __device__ float g_hsn[TOTPTS*64];   // after sn gather-max (then conv3 in-place)
static __device__ float g_h4 [TOTPTS*128];  // after conv4

__device__ __forceinline__ float lrelu(float v){ return fmaxf(v, 0.01f*v); }

// reference-order epilogue (identical codegen at every use site)
__device__ __forceinline__ float epi(float acc, float rn, float cn){
    return 2.f*acc - rn - cn;
}

__device__ __forceinline__ unsigned f2ord(float f){
    unsigned u = __float_as_uint(f);
    return (u & 0x80000000u) ? ~u : (u | 0x80000000u);
}

// ---- cp.async helpers ----
__device__ __forceinline__ void cpa4(unsigned dst, const float* src){
    asm volatile("cp.async.ca.shared.global [%0], [%1], 4;" :: "r"(dst), "l"(src));
}
__device__ __forceinline__ void cpa_commit(){ asm volatile("cp.async.commit_group;"); }
template<int N>
__device__ __forceinline__ void cpa_wait(){ asm volatile("cp.async.wait_group %0;" :: "n"(N)); }

__device__ __forceinline__ const float* pconv_in(int sel){
    switch(sel){ case 0: return g_h; case 1: return g_hdg; case 2: return g_p2;
                 case 3: return g_hsn; default: return g_hsn; }
}
__device__ __forceinline__ float* pconv_out(int sel){
    switch(sel){ case 0: return g_h; case 1: return g_p2; case 2: return g_p2;
                 case 3: return g_hsn; default: return g_h4; }
}

// ---------------- conv1: x(B,N,3) -> g_h (64ch) ----------------
__global__ void k_conv1(const float* __restrict__ x, const float* __restrict__ w,
                        const float* __restrict__ g, const float* __restrict__ b)
{
    __shared__ float sw[192], sg[64], sb[64];
    int t = threadIdx.x;
    if (t < 192) sw[t] = w[t];
    if (t < 64){ sg[t] = g[t]; sb[t] = b[t]; }
    __syncthreads();
    int lp = t >> 6, c = t & 63;
    int p  = blockIdx.x*4 + lp;
    float x0 = x[p*3+0], x1 = x[p*3+1], x2 = x[p*3+2];
    float v = sw[c*3+0]*x0 + sw[c*3+1]*x1 + sw[c*3+2]*x2;
    g_h[p*64+c] = lrelu(v*sg[c] + sb[c]);
}

// ---------------- pointwise conv 64 -> COUT with BN+LReLU; 8 point-groups per block ----------------
template<int COUT>
__global__ void k_pconv(int sel, const float* __restrict__ w,
                        const float* __restrict__ g, const float* __restrict__ b)
{
    const int PPB = 256/COUT;
    const int GRP = 8;
    __shared__ float wt[64*COUT];
    __shared__ float hs[PPB][64];
    __shared__ float sg[COUT], sb[COUT];
    const float* in  = pconv_in(sel);
    float*       out = pconv_out(sel);
    int t = threadIdx.x;
    for (int i = t; i < 64*COUT; i += 256){ int c = i>>6, k = i&63; wt[k*COUT+c] = w[i]; }
    for (int i = t; i < COUT;    i += 256){ sg[i] = g[i]; sb[i] = b[i]; }
    __syncthreads();
    int lp = t / COUT, c = t % COUT;
    float wr[64];
    #pragma unroll
    for (int k = 0; k < 64; k++) wr[k] = wt[k*COUT+c];
    float G = sg[c], Bv = sb[c];
    for (int g2 = 0; g2 < GRP; g2++){
        int p = (blockIdx.x*GRP + g2)*PPB + lp;
        __syncthreads();
        if (c < 64) hs[lp][c] = in[p*64+c];
        __syncthreads();
        float s = 0.f;
        #pragma unroll
        for (int k = 0; k < 64; k++) s += wr[k]*hs[lp][k];
        out[p*COUT+c] = lrelu(s*G + Bv);
    }
}

// ---------------- squared norms ----------------
__global__ void k_norms(const float* __restrict__ x)
{
    int p = blockIdx.x*256 + threadIdx.x;
    const float* hp = &g_h[p*64];
    float s = 0.f;
    #pragma unroll
    for (int k = 0; k < 64; k++){ float v = hp[k]; s += v*v; }
    g_nh[p] = s;
    float x0 = x[p*3], x1 = x[p*3+1], x2 = x[p*3+2];
    float sx = 0.f;
    sx = fmaf(x0,x0,sx); sx = fmaf(x1,x1,sx); sx = fmaf(x2,x2,sx);
    g_nx[p] = sx;
}

// ---------------- feature pair matrix: 128x128 tiles, 8x8 per thread,
//                  triangular tile grid; cp.async double-buffered K chunks;
//                  mirror via raw-dot smem staging (bit-exact both halves) ----------------
__global__ void __launch_bounds__(256, 2) k_pair(void)
{
    extern __shared__ float sBuf[];   // 4 buffers x 32x132 floats = 67584 B
    int b = blockIdx.y;
    const float* A  = g_h + (size_t)b*NPTS*64;
    const float* nn = g_nh + b*NPTS;
    float* pair = g_pair + (size_t)b*NPTS*NPTS;
    int t = threadIdx.x;

    int u = blockIdx.x;
    int bi = 0, rem = 32;
    while (u >= rem){ u -= rem; rem--; bi++; }
    int bj = bi + u;
    int r0 = bi*128, c0 = bj*128;

    unsigned sbase;
    { unsigned long long gp = __cvta_generic_to_shared(sBuf); sbase = (unsigned)gp; }

    // fill chunk kc into buffer pair kc (A at kc*2, B at kc*2+1)
    {
        int r = t >> 5, c = t & 31;          // 256 threads: 8 rows x 32 cols per step
        #pragma unroll
        for (int kc = 0; kc < 2; kc++){
            unsigned offA = (unsigned)((kc*2)   * 32*132);
            unsigned offB = (unsigned)((kc*2+1) * 32*132);
            #pragma unroll
            for (int s = 0; s < 16; s++){
                int rr = r + s*8;             // 0..127
                cpa4(sbase + (offA + c*132 + rr)*4u, &A[(size_t)(r0+rr)*64 + kc*32 + c]);
                cpa4(sbase + (offB + c*132 + rr)*4u, &A[(size_t)(c0+rr)*64 + kc*32 + c]);
            }
            cpa_commit();
        }
    }

    int ty = t >> 4, tx = t & 15;
    float acc[8][8];
    #pragma unroll
    for (int i = 0; i < 8; i++)
        #pragma unroll
        for (int j = 0; j < 8; j++) acc[i][j] = 0.f;

    #pragma unroll
    for (int kc = 0; kc < 2; kc++){
        if (kc == 0) cpa_wait<1>(); else cpa_wait<0>();
        __syncthreads();
        float (*sA)[132] = (float(*)[132])(sBuf + (kc*2)  *32*132);
        float (*sB)[132] = (float(*)[132])(sBuf + (kc*2+1)*32*132);
        #pragma unroll
        for (int c = 0; c < 32; c++){
            float4 a0 = *(const float4*)&sA[c][ty*4];
            float4 a1 = *(const float4*)&sA[c][ty*4+64];
            float4 b0 = *(const float4*)&sB[c][tx*4];
            float4 b1 = *(const float4*)&sB[c][tx*4+64];
            float av[8] = {a0.x,a0.y,a0.z,a0.w,a1.x,a1.y,a1.z,a1.w};
            float bv[8] = {b0.x,b0.y,b0.z,b0.w,b1.x,b1.y,b1.z,b1.w};
            #pragma unroll
            for (int i = 0; i < 8; i++)
                #pragma unroll
                for (int j = 0; j < 8; j++) acc[i][j] += av[i]*bv[j];
        }
    }

    float cnv[8];
    #pragma unroll
    for (int j = 0; j < 8; j++) cnv[j] = nn[c0 + ((j>>2)<<6) + tx*4 + (j&3)];
    #pragma unroll
    for (int i = 0; i < 8; i++){
        int gr = r0 + ((i>>2)<<6) + ty*4 + (i&3);
        float rn = nn[gr];
        float4 o0, o1;
        o0.x = epi(acc[i][0], rn, cnv[0]);
        o0.y = epi(acc[i][1], rn, cnv[1]);
        o0.z = epi(acc[i][2], rn, cnv[2]);
        o0.w = epi(acc[i][3], rn, cnv[3]);
        o1.x = epi(acc[i][4], rn, cnv[4]);
        o1.y = epi(acc[i][5], rn, cnv[5]);
        o1.z = epi(acc[i][6], rn, cnv[6]);
        o1.w = epi(acc[i][7], rn, cnv[7]);
        *(float4*)&pair[(size_t)gr*NPTS + c0 + tx*4]      = o0;
        *(float4*)&pair[(size_t)gr*NPTS + c0 + 64 + tx*4] = o1;
    }

    if (bi != bj){
        // mirror: stage RAW dot products transposed (64 rows x 128 cols, stride 132)
        float (*sM)[132] = (float(*)[132])sBuf;
        #pragma unroll
        for (int h = 0; h < 2; h++){
            __syncthreads();
            #pragma unroll
            for (int i = 0; i < 8; i++){
                int lr = ((i>>2)<<6) + ty*4 + (i&3);
                #pragma unroll
                for (int q = 0; q < 4; q++)
                    sM[tx*4+q][lr] = acc[i][4*h+q];
            }
            __syncthreads();
            for (int i = t; i < 64*128; i += 256){
                int a = i >> 7, col = i & 127;
                int gr = c0 + h*64 + a;
                pair[(size_t)gr*NPTS + r0 + col] = epi(sM[a][col], nn[gr], nn[r0+col]);
            }
        }
    }
}

// ---------------- radix digit finder (descending bins), warp 0 ----------------
__device__ __forceinline__ void find_digit(unsigned* hist, unsigned remk, unsigned* sc)
{
    int t = threadIdx.x, lane = t & 31;
    if (t < 32){
        int base = 255 - 8*lane;
        unsigned bl[8]; unsigned ssum = 0;
        #pragma unroll
        for (int q = 0; q < 8; q++){ bl[q] = hist[base - q]; ssum += bl[q]; }
        unsigned cum = ssum;
        #pragma unroll
        for (int o = 1; o < 32; o <<= 1){
            unsigned vv = __shfl_up_sync(0xffffffffu, cum, o);
            if (lane >= o) cum += vv;
        }
        unsigned before = cum - ssum;
        if (before < remk && remk <= cum){
            unsigned c2 = before; int dig = base; unsigned r2 = 1; bool fnd = false;
            #pragma unroll
            for (int q = 0; q < 8; q++){
                if (!fnd && c2 + bl[q] >= remk){ dig = base - q; r2 = remk - c2; fnd = true; }
                c2 += bl[q];
            }
            sc[0] = (unsigned)dig; sc[1] = r2;
        }
    }
}

// ---------------- warp-aggregated histogram add for one ordered value ----------------
__device__ __forceinline__ void hist_add(unsigned* hist, unsigned v, int lane)
{
    unsigned bin = v >> 24;
    unsigned m = __match_any_sync(0xffffffffu, bin);
    if ((m & ((1u << lane) - 1u)) == 0u) atomicAdd(&hist[bin], (unsigned)__popc(m));
}

// ---------------- select rest: pass-1 histogram ALREADY populated by caller.
//                  uint4-vectorized scans; exact top-20;
//                  key = (ordval<<32)|(4095-idx): value desc, index asc ----------------
__device__ __forceinline__ void top20_select_posthist(
    unsigned* vals, unsigned* hist,
    unsigned long long* gtlist, unsigned* eqlow, unsigned* sc, int* out)
{
    int t = threadIdx.x, lane = t & 31;
    __syncthreads();
    find_digit(hist, KNN, sc);
    __syncthreads();
    unsigned prefix = sc[0] << 24;
    unsigned remk   = sc[1];

    // passes 2..4 (vectorized): only prefix-matching elements hit the histogram
    #pragma unroll
    for (int d = 2; d >= 0; d--){
        __syncthreads();
        hist[t] = 0;
        __syncthreads();
        int sh = d*8;
        unsigned pmask = 0xFFFFFFFFu << (sh + 8);
        for (int j = t; j < NPTS/4; j += 256){
            uint4 v = *(const uint4*)&vals[4*j];
            if ((v.x & pmask) == prefix) atomicAdd(&hist[(v.x >> sh) & 255u], 1u);
            if ((v.y & pmask) == prefix) atomicAdd(&hist[(v.y >> sh) & 255u], 1u);
            if ((v.z & pmask) == prefix) atomicAdd(&hist[(v.z >> sh) & 255u], 1u);
            if ((v.w & pmask) == prefix) atomicAdd(&hist[(v.w >> sh) & 255u], 1u);
        }
        __syncthreads();
        find_digit(hist, remk, sc);
        __syncthreads();
        prefix |= sc[0] << sh;
        remk = sc[1];
    }
    unsigned thresh = prefix;

    // collect (vectorized): strictly-greater keys + equal-valued tie indices
    for (int j = t; j < NPTS/4; j += 256){
        uint4 v = *(const uint4*)&vals[4*j];
        #pragma unroll
        for (int q = 0; q < 4; q++){
            unsigned vv = (q==0)?v.x:(q==1)?v.y:(q==2)?v.z:v.w;
            if (vv > thresh){
                unsigned p = atomicAdd(&sc[2], 1u);
                if (p < 32) gtlist[p] = ((unsigned long long)vv << 32) | (unsigned)(NPTS - 1 - (4*j+q));
            } else if (vv == thresh){
                unsigned p = atomicAdd(&sc[3], 1u);
                if (p < 64) eqlow[p] = (unsigned)(NPTS - 1 - (4*j+q));
            }
        }
    }
    __syncthreads();

    // warp 0 emits the 20 results in (value desc, index asc) order
    if (t < 32){
        unsigned cgt = sc[2];
        unsigned ceq = sc[3] < 64u ? sc[3] : 64u;
        unsigned tot = cgt + ceq;
        unsigned long long tk = (unsigned long long)thresh << 32;
        unsigned long long k0 = 0ull, k1 = 0ull;
        if ((unsigned)lane < tot)
            k0 = ((unsigned)lane < cgt) ? gtlist[lane] : (tk | eqlow[lane - cgt]);
        if ((unsigned)(lane + 32) < tot)
            k1 = tk | eqlow[lane + 32 - cgt];
        for (int it = 0; it < KNN; it++){
            unsigned long long r = (k0 > k1) ? k0 : k1;
            #pragma unroll
            for (int o = 16; o; o >>= 1){
                unsigned long long other = __shfl_xor_sync(0xffffffffu, r, o);
                if (other > r) r = other;
            }
            if (k0 == r) k0 = 0ull;
            else if (k1 == r) k1 = 0ull;
            if (lane == 0) out[it] = (NPTS - 1) - (int)(r & 0xFFFFFFFFu);
        }
    }
}

// ---------------- feature top-k: block per (row, batch); pass-1 fused into load ----------------
__global__ void k_topk(void)
{
    __shared__ __align__(16) unsigned int vals[NPTS];
    __shared__ unsigned int hist[256];
    __shared__ unsigned long long gtlist[32];
    __shared__ unsigned int eqlow[64];
    __shared__ unsigned int sc[8];

    int t = threadIdx.x, lane = t & 31;
    int row = blockIdx.x, b = blockIdx.y;
    hist[t] = 0;
    if (t == 0){ sc[2] = 0; sc[3] = 0; }
    __syncthreads();

    const float4* pr = (const float4*)(g_pair + (size_t)b*NPTS*NPTS + (size_t)row*NPTS);
    for (int j = t; j < NPTS/4; j += 256){
        float4 v = __ldg(&pr[j]);
        uint4 o; o.x = f2ord(v.x); o.y = f2ord(v.y); o.z = f2ord(v.z); o.w = f2ord(v.w);
        *(uint4*)&vals[4*j] = o;
        hist_add(hist, o.x, lane);
        hist_add(hist, o.y, lane);
        hist_add(hist, o.z, lane);
        hist_add(hist, o.w, lane);
    }
    int* out = g_idx1 + ((size_t)b*NPTS + row)*KNN;
    top20_select_posthist(vals, hist, gtlist, eqlow, sc, out);
}

// ---------------- coordinate KNN, fused distance + select; pass-1 fused into compute ----------------
__global__ void k_knn3(const float* __restrict__ x)
{
    __shared__ __align__(16) unsigned int vals[NPTS];
    __shared__ unsigned int hist[256];
    __shared__ unsigned long long gtlist[32];
    __shared__ unsigned int eqlow[64];
    __shared__ unsigned int sc[8];

    int t = threadIdx.x, lane = t & 31;
    int row = blockIdx.x, b = blockIdx.y;
    hist[t] = 0;
    if (t == 0){ sc[2] = 0; sc[3] = 0; }
    __syncthreads();

    const float* xb = x + (size_t)b*NPTS*3;
    const float* nn = g_nx + b*NPTS;
    float xr0 = xb[row*3+0], xr1 = xb[row*3+1], xr2 = xb[row*3+2];
    float rn = nn[row];
    for (int i = t; i < NPTS; i += 256){
        float m0 = __ldg(&xb[i*3+0]), m1 = __ldg(&xb[i*3+1]), m2 = __ldg(&xb[i*3+2]);
        float s = 0.f;
        s = fmaf(xr0, m0, s); s = fmaf(xr1, m1, s); s = fmaf(xr2, m2, s);
        unsigned v = f2ord(epi(s, rn, nn[i]));
        vals[i] = v;
        hist_add(hist, v, lane);
    }
    int* out = g_idx2 + ((size_t)b*NPTS + row)*KNN;
    top20_select_posthist(vals, hist, gtlist, eqlow, sc, out);
}

// ---------------- dg precompute: a = (Wc-Wd)@h, u = Wd@h; 8 groups per block ----------------
__global__ void k_dgpre(const float* __restrict__ wdg1)
{
    __shared__ float wct[64*64], wdt[64*64];
    __shared__ float hs[4][64];
    int t = threadIdx.x;
    for (int i = t; i < 4096; i += 256){
        int c = i>>6, k = i&63;
        float wc = wdg1[c*128 + k], wd = wdg1[c*128 + 64 + k];
        wdt[k*64+c] = wd;
        wct[k*64+c] = wc - wd;
    }
    __syncthreads();
    int lp = t>>6, c = t&63;
    float wa[64], wu[64];
    #pragma unroll
    for (int k = 0; k < 64; k++){ wa[k] = wct[k*64+c]; wu[k] = wdt[k*64+c]; }
    for (int g2 = 0; g2 < 8; g2++){
        int p = (blockIdx.x*8 + g2)*4 + lp;
        __syncthreads();
        hs[lp][c] = g_h[p*64+c];
        __syncthreads();
        float sa = 0.f, su = 0.f;
        #pragma unroll
        for (int k = 0; k < 64; k++){ float h = hs[lp][k]; sa += wa[k]*h; su += wu[k]*h; }
        g_a[p*64+c] = sa;
        g_u[p*64+c] = su;
    }
}

// ---------------- dg edge conv, two-phase (4 pts/block, 1 ch/thread) ----------------
__global__ void k_dgedge(const float* __restrict__ w2,
                         const float* __restrict__ g1v, const float* __restrict__ b1v,
                         const float* __restrict__ g2v, const float* __restrict__ b2v)
{
    __shared__ float wt[4096];
    __shared__ float t1s[4][KNN][64];
    __shared__ float sg1[64], sb1[64], sg2[64], sb2[64];
    int t = threadIdx.x;
    for (int i = t; i < 4096; i += 256){ int c = i>>6, k = i&63; wt[k*64+c] = w2[i]; }
    if (t < 64){ sg1[t] = g1v[t]; sb1[t] = b1v[t]; sg2[t] = g2v[t]; sb2[t] = b2v[t]; }
    __syncthreads();
    int lp = t>>6, c = t&63;
    int p    = blockIdx.x*4 + lp;
    int base = (p >> 12) * NPTS;
    float ac = g_a[p*64+c];
    float G1 = sg1[c], B1 = sb1[c], G2 = sg2[c], B2 = sb2[c];
    const int* ip = &g_idx1[p*KNN];
    #pragma unroll 5
    for (int j = 0; j < KNN; j++){
        int m = ip[j];
        float v = (ac + g_u[(base+m)*64 + c]) * G1 + B1;
        t1s[lp][j][c] = lrelu(v);
    }
    float wr[64];
    #pragma unroll
    for (int k = 0; k < 64; k++) wr[k] = wt[k*64+c];
    __syncthreads();
    float mx = -3.4e38f;
    for (int j = 0; j < KNN; j++){
        const float4* tp4 = (const float4*)t1s[lp][j];
        float s = 0.f;
        #pragma unroll
        for (int k4 = 0; k4 < 16; k4++){
            float4 hv = tp4[k4];
            s += wr[4*k4+0]*hv.x + wr[4*k4+1]*hv.y + wr[4*k4+2]*hv.z + wr[4*k4+3]*hv.w;
        }
        s = lrelu(s*G2 + B2);
        mx = fmaxf(mx, s);
    }
    g_hdg[p*64+c] = mx;
}

// ---------------- sn branch: gather-max of per-point MLP output ----------------
__global__ void k_snmax()
{
    int t = threadIdx.x;
    int lp = t>>6, c = t&63;
    int p    = blockIdx.x*4 + lp;
    int base = (p >> 12) * NPTS;
    const int* ip = &g_idx2[p*KNN];
    float mx = -3.4e38f;
    for (int j = 0; j < KNN; j++){
        int m = ip[j];
        mx = fmaxf(mx, g_p2[(base+m)*64 + c]);
    }
    g_hsn[p*64+c] = mx;
}

// ---------------- conv5 GEMM (64x64 tiles, 4x4 per thread) ----------------
__global__ void k_conv5(const float* __restrict__ w5, const float* __restrict__ g5,
                        const float* __restrict__ b5, float* __restrict__ out)
{
    __shared__ float wt[64][68];
    __shared__ float ht[64][68];
    int t   = threadIdx.x;
    int co0 = blockIdx.y*64;
    int pt0 = blockIdx.x*64;
    int tr = (t>>4)<<2, tc = (t&15)<<2;
    float acc[4][4] = {{0.f,0.f,0.f,0.f},{0.f,0.f,0.f,0.f},{0.f,0.f,0.f,0.f},{0.f,0.f,0.f,0.f}};
    for (int kc = 0; kc < 2; kc++){
        __syncthreads();
        for (int i = t; i < 4096; i += 256){ int c = i>>6, k = i&63; wt[k][c] = w5[(co0+c)*128 + kc*64 + k]; }
        for (int i = t; i < 4096; i += 256){ int q = i>>6, k = i&63; ht[k][q] = g_h4[(size_t)(pt0+q)*128 + kc*64 + k]; }
        __syncthreads();
        #pragma unroll
        for (int k = 0; k < 64; k++){
            float4 wv = *(const float4*)&wt[k][tr];
            float4 hv = *(const float4*)&ht[k][tc];
            acc[0][0] += wv.x*hv.x; acc[0][1] += wv.x*hv.y; acc[0][2] += wv.x*hv.z; acc[0][3] += wv.x*hv.w;
            acc[1][0] += wv.y*hv.x; acc[1][1] += wv.y*hv.y; acc[1][2] += wv.y*hv.z; acc[1][3] += wv.y*hv.w;
            acc[2][0] += wv.z*hv.x; acc[2][1] += wv.z*hv.y; acc[2][2] += wv.z*hv.z; acc[2][3] += wv.z*hv.w;
            acc[3][0] += wv.w*hv.x; acc[3][1] += wv.w*hv.y; acc[3][2] += wv.w*hv.z; acc[3][3] += wv.w*hv.w;
        }
    }
    int bI = pt0 >> 12;
    int n0 = (pt0 + tc) & (NPTS-1);
    #pragma unroll
    for (int i = 0; i < 4; i++){
        int co = co0 + tr + i;
        float G = g5[co], Bv = b5[co];
        float4 o;
        o.x = lrelu(acc[i][0]*G + Bv);
        o.y = lrelu(acc[i][1]*G + Bv);
        o.z = lrelu(acc[i][2]*G + Bv);
        o.w = lrelu(acc[i][3]*G + Bv);
        *(float4*)&out[((size_t)bI*512 + co)*NPTS + n0] = o;
    }
}

// ---------------- launch ----------------
extern "C" void kernel_launch(void* const* d_in, const int* in_sizes, int n_in,
                              void* d_out, int out_size)
{
    const float* x    = (const float*)d_in[0];
    const float* w1   = (const float*)d_in[1];
    const float* g1   = (const float*)d_in[2];
    const float* b1   = (const float*)d_in[3];
    const float* w2   = (const float*)d_in[4];
    const float* g2   = (const float*)d_in[5];
    const float* b2   = (const float*)d_in[6];
    const float* wdg1 = (const float*)d_in[7];
    const float* gdg1 = (const float*)d_in[8];
    const float* bdg1 = (const float*)d_in[9];
    const float* wdg2 = (const float*)d_in[10];
    const float* gdg2 = (const float*)d_in[11];
    const float* bdg2 = (const float*)d_in[12];
    const float* wsn1 = (const float*)d_in[13];
    const float* gsn1 = (const float*)d_in[14];
    const float* bsn1 = (const float*)d_in[15];
    const float* wsn2 = (const float*)d_in[16];
    const float* gsn2 = (const float*)d_in[17];
    const float* bsn2 = (const float*)d_in[18];
    const float* w3   = (const float*)d_in[19];
    const float* g3   = (const float*)d_in[20];
    const float* b3   = (const float*)d_in[21];
    const float* w4   = (const float*)d_in[22];
    const float* g4   = (const float*)d_in[23];
    const float* b4   = (const float*)d_in[24];
    const float* w5   = (const float*)d_in[25];
    const float* g5   = (const float*)d_in[26];
    const float* b5   = (const float*)d_in[27];

    float* out  = (float*)d_out;

    const int PAIR_SMEM = 4*32*132*4;   // 67584 B dynamic smem
    static int attr_done = 0;
    if (!attr_done){
        cudaFuncSetAttribute(k_pair, cudaFuncAttributeMaxDynamicSharedMemorySize, PAIR_SMEM);
        attr_done = 1;
    }

    // conv1 + conv2 (in-place) + norms
    k_conv1    <<<TOTPTS/4,  256>>>(x, w1, g1, b1);
    k_pconv<64><<<TOTPTS/32, 256>>>(0, w2, g2, b2);
    k_norms    <<<TOTPTS/256,256>>>(x);

    const int NTILE = 32*33/2;   // 528 upper-triangular 128x128 tiles
    // feature KNN (all batches, single launches)
    k_pair<<<dim3(NTILE, BB), 256, PAIR_SMEM>>>();
    k_topk<<<dim3(NPTS,  BB), 256>>>();
    // coordinate KNN (fused distance + select)
    k_knn3<<<dim3(NPTS,  BB), 256>>>(x);

    // dg branch
    k_dgpre <<<TOTPTS/32, 256>>>(wdg1);
    k_dgedge<<<TOTPTS/4,  256>>>(wdg2, gdg1, bdg1, gdg2, bdg2);

    // sn branch: per-point MLP then gather-max
    k_pconv<64><<<TOTPTS/32, 256>>>(1, wsn1, gsn1, bsn1);
    k_pconv<64><<<TOTPTS/32, 256>>>(2, wsn2, gsn2, bsn2);
    k_snmax    <<<TOTPTS/4,  256>>>();

    // head
    k_pconv<64> <<<TOTPTS/32, 256>>>(3, w3, g3, b3);
    k_pconv<128><<<TOTPTS/16, 256>>>(4, w4, g4, b4);
    k_conv5     <<<dim3(TOTPTS/64, 512/64), 256>>>(w5, g5, b5, out);
}

// round 13
// speedup vs baseline: 1.1616x; 1.0078x over previous
#include <cuda_runtime.h>

#define BB    8
#define NPTS  4096
#define KNN   20
#define TOTPTS (BB*NPTS)

// ---------------- static device scratch (sanctioned workaround) ----------------
static __device__ float g_pair[(size_t)BB*NPTS*NPTS]; // 512MB: all 8 batches' pair matrices
static __device__ float g_h  [TOTPTS*64];   // features after conv1+conv2, (B,N,64)
static __device__ float g_nh [TOTPTS];      // ||h||^2
static __device__ int   g_idx1[TOTPTS*KNN];
static __device__ int   g_idx2[TOTPTS*KNN];
static __device__ float g_a  [TOTPTS*64];   // (Wc-Wd)@h
static __device__ float g_u  [TOTPTS*64];   // Wd@h
static __device__ float g_hdg[TOTPTS*64];   // after dg branch max
static __device__ float g_p2 [TOTPTS*64];   // sn-branch per-point MLP output
static __device__ float g_hsn[TOTPTS*64];   // after sn gather-max (then conv3 in-place)
static __device__ float g_h4 [TOTPTS*128];  // after conv4

__device__ __forceinline__ float lrelu(float v){ return fmaxf(v, 0.01f*v); }

// reference-order epilogue (identical codegen at every use site)
__device__ __forceinline__ float epi(float acc, float rn, float cn){
    return 2.f*acc - rn - cn;
}

__device__ __forceinline__ unsigned f2ord(float f){
    unsigned u = __float_as_uint(f);
    return (u & 0x80000000u) ? ~u : (u | 0x80000000u);
}

// ---- cp.async helpers ----
__device__ __forceinline__ void cpa4(unsigned dst, const float* src){
    asm volatile("cp.async.ca.shared.global [%0], [%1], 4;" :: "r"(dst), "l"(src));
}
__device__ __forceinline__ void cpa_commit(){ asm volatile("cp.async.commit_group;"); }
template<int N>
__device__ __forceinline__ void cpa_wait(){ asm volatile("cp.async.wait_group %0;" :: "n"(N)); }

__device__ __forceinline__ const float* pconv_in(int sel){
    switch(sel){ case 1: return g_hdg; case 2: return g_p2;
                 case 3: return g_hsn; default: return g_hsn; }
}
__device__ __forceinline__ float* pconv_out(int sel){
    switch(sel){ case 1: return g_p2; case 2: return g_p2;
                 case 3: return g_hsn; default: return g_h4; }
}

// ---------------- fused conv1+conv2: x(B,N,3) -> g_h (64ch); 8 groups of 4 pts ----------------
__global__ void k_conv12(const float* __restrict__ x,
                         const float* __restrict__ w1, const float* __restrict__ g1,
                         const float* __restrict__ b1,
                         const float* __restrict__ w2, const float* __restrict__ g2,
                         const float* __restrict__ b2)
{
    __shared__ float sw[192], sg1[64], sb1[64];
    __shared__ float wt[4096];         // transposed w2: wt[k*64+c]
    __shared__ float sg2[64], sb2[64];
    __shared__ float h1s[4][64];
    int t = threadIdx.x;
    if (t < 192) sw[t] = w1[t];
    if (t < 64){ sg1[t] = g1[t]; sb1[t] = b1[t]; sg2[t] = g2[t]; sb2[t] = b2[t]; }
    for (int i = t; i < 4096; i += 256){ int c = i>>6, k = i&63; wt[k*64+c] = w2[i]; }
    __syncthreads();
    int lp = t >> 6, c = t & 63;
    float wr[64];
    #pragma unroll
    for (int k = 0; k < 64; k++) wr[k] = wt[k*64+c];
    float W0 = sw[c*3+0], W1 = sw[c*3+1], W2 = sw[c*3+2];
    float Ga = sg1[c], Ba = sb1[c], Gb = sg2[c], Bb = sb2[c];
    for (int g = 0; g < 8; g++){
        int p = (blockIdx.x*8 + g)*4 + lp;
        __syncthreads();
        float x0 = x[p*3+0], x1 = x[p*3+1], x2 = x[p*3+2];
        float v = W0*x0 + W1*x1 + W2*x2;
        h1s[lp][c] = lrelu(v*Ga + Ba);
        __syncthreads();
        float s = 0.f;
        #pragma unroll
        for (int k = 0; k < 64; k++) s += wr[k]*h1s[lp][k];
        g_h[p*64+c] = lrelu(s*Gb + Bb);
    }
}

// ---------------- pointwise conv 64 -> COUT with BN+LReLU; 8 point-groups per block ----------------
template<int COUT>
__global__ void k_pconv(int sel, const float* __restrict__ w,
                        const float* __restrict__ g, const float* __restrict__ b)
{
    const int PPB = 256/COUT;
    const int GRP = 8;
    __shared__ float wt[64*COUT];
    __shared__ float hs[PPB][64];
    __shared__ float sg[COUT], sb[COUT];
    const float* in  = pconv_in(sel);
    float*       out = pconv_out(sel);
    int t = threadIdx.x;
    for (int i = t; i < 64*COUT; i += 256){ int c = i>>6, k = i&63; wt[k*COUT+c] = w[i]; }
    for (int i = t; i < COUT;    i += 256){ sg[i] = g[i]; sb[i] = b[i]; }
    __syncthreads();
    int lp = t / COUT, c = t % COUT;
    float wr[64];
    #pragma unroll
    for (int k = 0; k < 64; k++) wr[k] = wt[k*COUT+c];
    float G = sg[c], Bv = sb[c];
    for (int g2 = 0; g2 < GRP; g2++){
        int p = (blockIdx.x*GRP + g2)*PPB + lp;
        __syncthreads();
        if (c < 64) hs[lp][c] = in[p*64+c];
        __syncthreads();
        float s = 0.f;
        #pragma unroll
        for (int k = 0; k < 64; k++) s += wr[k]*hs[lp][k];
        out[p*COUT+c] = lrelu(s*G + Bv);
    }
}

// ---------------- squared norm of h only (x-norms computed inline in select) ----------------
__global__ void k_norms(void)
{
    int p = blockIdx.x*256 + threadIdx.x;
    const float* hp = &g_h[p*64];
    float s = 0.f;
    #pragma unroll
    for (int k = 0; k < 64; k++){ float v = hp[k]; s += v*v; }
    g_nh[p] = s;
}

// ---------------- feature pair matrix: 128x128 tiles, 8x8 per thread,
//                  triangular tile grid; cp.async double-buffered K chunks;
//                  mirror via raw-dot smem staging (bit-exact both halves) ----------------
__global__ void __launch_bounds__(256, 2) k_pair(void)
{
    extern __shared__ float sBuf[];   // 4 buffers x 32x132 floats = 67584 B
    int b = blockIdx.y;
    const float* A  = g_h + (size_t)b*NPTS*64;
    const float* nn = g_nh + b*NPTS;
    float* pair = g_pair + (size_t)b*NPTS*NPTS;
    int t = threadIdx.x;

    int u = blockIdx.x;
    int bi = 0, rem = 32;
    while (u >= rem){ u -= rem; rem--; bi++; }
    int bj = bi + u;
    int r0 = bi*128, c0 = bj*128;

    unsigned sbase;
    { unsigned long long gp = __cvta_generic_to_shared(sBuf); sbase = (unsigned)gp; }

    {
        int r = t >> 5, c = t & 31;
        #pragma unroll
        for (int kc = 0; kc < 2; kc++){
            unsigned offA = (unsigned)((kc*2)   * 32*132);
            unsigned offB = (unsigned)((kc*2+1) * 32*132);
            #pragma unroll
            for (int s = 0; s < 16; s++){
                int rr = r + s*8;
                cpa4(sbase + (offA + c*132 + rr)*4u, &A[(size_t)(r0+rr)*64 + kc*32 + c]);
                cpa4(sbase + (offB + c*132 + rr)*4u, &A[(size_t)(c0+rr)*64 + kc*32 + c]);
            }
            cpa_commit();
        }
    }

    int ty = t >> 4, tx = t & 15;
    float acc[8][8];
    #pragma unroll
    for (int i = 0; i < 8; i++)
        #pragma unroll
        for (int j = 0; j < 8; j++) acc[i][j] = 0.f;

    #pragma unroll
    for (int kc = 0; kc < 2; kc++){
        if (kc == 0) cpa_wait<1>(); else cpa_wait<0>();
        __syncthreads();
        float (*sA)[132] = (float(*)[132])(sBuf + (kc*2)  *32*132);
        float (*sB)[132] = (float(*)[132])(sBuf + (kc*2+1)*32*132);
        #pragma unroll
        for (int c = 0; c < 32; c++){
            float4 a0 = *(const float4*)&sA[c][ty*4];
            float4 a1 = *(const float4*)&sA[c][ty*4+64];
            float4 b0 = *(const float4*)&sB[c][tx*4];
            float4 b1 = *(const float4*)&sB[c][tx*4+64];
            float av[8] = {a0.x,a0.y,a0.z,a0.w,a1.x,a1.y,a1.z,a1.w};
            float bv[8] = {b0.x,b0.y,b0.z,b0.w,b1.x,b1.y,b1.z,b1.w};
            #pragma unroll
            for (int i = 0; i < 8; i++)
                #pragma unroll
                for (int j = 0; j < 8; j++) acc[i][j] += av[i]*bv[j];
        }
    }

    float cnv[8];
    #pragma unroll
    for (int j = 0; j < 8; j++) cnv[j] = nn[c0 + ((j>>2)<<6) + tx*4 + (j&3)];
    #pragma unroll
    for (int i = 0; i < 8; i++){
        int gr = r0 + ((i>>2)<<6) + ty*4 + (i&3);
        float rn = nn[gr];
        float4 o0, o1;
        o0.x = epi(acc[i][0], rn, cnv[0]);
        o0.y = epi(acc[i][1], rn, cnv[1]);
        o0.z = epi(acc[i][2], rn, cnv[2]);
        o0.w = epi(acc[i][3], rn, cnv[3]);
        o1.x = epi(acc[i][4], rn, cnv[4]);
        o1.y = epi(acc[i][5], rn, cnv[5]);
        o1.z = epi(acc[i][6], rn, cnv[6]);
        o1.w = epi(acc[i][7], rn, cnv[7]);
        *(float4*)&pair[(size_t)gr*NPTS + c0 + tx*4]      = o0;
        *(float4*)&pair[(size_t)gr*NPTS + c0 + 64 + tx*4] = o1;
    }

    if (bi != bj){
        float (*sM)[132] = (float(*)[132])sBuf;
        #pragma unroll
        for (int h = 0; h < 2; h++){
            __syncthreads();
            #pragma unroll
            for (int i = 0; i < 8; i++){
                int lr = ((i>>2)<<6) + ty*4 + (i&3);
                #pragma unroll
                for (int q = 0; q < 4; q++)
                    sM[tx*4+q][lr] = acc[i][4*h+q];
            }
            __syncthreads();
            for (int i = t; i < 64*128; i += 256){
                int a = i >> 7, col = i & 127;
                int gr = c0 + h*64 + a;
                pair[(size_t)gr*NPTS + r0 + col] = epi(sM[a][col], nn[gr], nn[r0+col]);
            }
        }
    }
}

// ---------------- radix digit finder (descending bins), warp 0 ----------------
__device__ __forceinline__ void find_digit(unsigned* hist, unsigned remk, unsigned* sc)
{
    int t = threadIdx.x, lane = t & 31;
    if (t < 32){
        int base = 255 - 8*lane;
        unsigned bl[8]; unsigned ssum = 0;
        #pragma unroll
        for (int q = 0; q < 8; q++){ bl[q] = hist[base - q]; ssum += bl[q]; }
        unsigned cum = ssum;
        #pragma unroll
        for (int o = 1; o < 32; o <<= 1){
            unsigned vv = __shfl_up_sync(0xffffffffu, cum, o);
            if (lane >= o) cum += vv;
        }
        unsigned before = cum - ssum;
        if (before < remk && remk <= cum){
            unsigned c2 = before; int dig = base; unsigned r2 = 1; bool fnd = false;
            #pragma unroll
            for (int q = 0; q < 8; q++){
                if (!fnd && c2 + bl[q] >= remk){ dig = base - q; r2 = remk - c2; fnd = true; }
                c2 += bl[q];
            }
            sc[0] = (unsigned)dig; sc[1] = r2;
        }
    }
}

// ---------------- warp-aggregated histogram add for one ordered value ----------------
__device__ __forceinline__ void hist_add(unsigned* hist, unsigned v, int lane)
{
    unsigned bin = v >> 24;
    unsigned m = __match_any_sync(0xffffffffu, bin);
    if ((m & ((1u << lane) - 1u)) == 0u) atomicAdd(&hist[bin], (unsigned)__popc(m));
}

// ---------------- select rest: pass-1 histogram ALREADY populated by caller.
//                  uint4-vectorized scans; exact top-20;
//                  key = (ordval<<32)|(4095-idx): value desc, index asc ----------------
__device__ __forceinline__ void top20_select_posthist(
    unsigned* vals, unsigned* hist,
    unsigned long long* gtlist, unsigned* eqlow, unsigned* sc, int* out)
{
    int t = threadIdx.x, lane = t & 31;
    __syncthreads();
    find_digit(hist, KNN, sc);
    __syncthreads();
    unsigned prefix = sc[0] << 24;
    unsigned remk   = sc[1];

    #pragma unroll
    for (int d = 2; d >= 0; d--){
        __syncthreads();
        hist[t] = 0;
        __syncthreads();
        int sh = d*8;
        unsigned pmask = 0xFFFFFFFFu << (sh + 8);
        for (int j = t; j < NPTS/4; j += 256){
            uint4 v = *(const uint4*)&vals[4*j];
            if ((v.x & pmask) == prefix) atomicAdd(&hist[(v.x >> sh) & 255u], 1u);
            if ((v.y & pmask) == prefix) atomicAdd(&hist[(v.y >> sh) & 255u], 1u);
            if ((v.z & pmask) == prefix) atomicAdd(&hist[(v.z >> sh) & 255u], 1u);
            if ((v.w & pmask) == prefix) atomicAdd(&hist[(v.w >> sh) & 255u], 1u);
        }
        __syncthreads();
        find_digit(hist, remk, sc);
        __syncthreads();
        prefix |= sc[0] << sh;
        remk = sc[1];
    }
    unsigned thresh = prefix;

    for (int j = t; j < NPTS/4; j += 256){
        uint4 v = *(const uint4*)&vals[4*j];
        #pragma unroll
        for (int q = 0; q < 4; q++){
            unsigned vv = (q==0)?v.x:(q==1)?v.y:(q==2)?v.z:v.w;
            if (vv > thresh){
                unsigned p = atomicAdd(&sc[2], 1u);
                if (p < 32) gtlist[p] = ((unsigned long long)vv << 32) | (unsigned)(NPTS - 1 - (4*j+q));
            } else if (vv == thresh){
                unsigned p = atomicAdd(&sc[3], 1u);
                if (p < 64) eqlow[p] = (unsigned)(NPTS - 1 - (4*j+q));
            }
        }
    }
    __syncthreads();

    if (t < 32){
        unsigned cgt = sc[2];
        unsigned ceq = sc[3] < 64u ? sc[3] : 64u;
        unsigned tot = cgt + ceq;
        unsigned long long tk = (unsigned long long)thresh << 32;
        unsigned long long k0 = 0ull, k1 = 0ull;
        if ((unsigned)lane < tot)
            k0 = ((unsigned)lane < cgt) ? gtlist[lane] : (tk | eqlow[lane - cgt]);
        if ((unsigned)(lane + 32) < tot)
            k1 = tk | eqlow[lane + 32 - cgt];
        for (int it = 0; it < KNN; it++){
            unsigned long long r = (k0 > k1) ? k0 : k1;
            #pragma unroll
            for (int o = 16; o; o >>= 1){
                unsigned long long other = __shfl_xor_sync(0xffffffffu, r, o);
                if (other > r) r = other;
            }
            if (k0 == r) k0 = 0ull;
            else if (k1 == r) k1 = 0ull;
            if (lane == 0) out[it] = (NPTS - 1) - (int)(r & 0xFFFFFFFFu);
        }
    }
}

// ---------------- combined select: even blocks = feature top-k (memory-bound),
//                  odd blocks = coordinate KNN (compute-bound) -> co-resident overlap ----------------
__global__ void k_select(const float* __restrict__ x)
{
    __shared__ __align__(16) unsigned int vals[NPTS];
    __shared__ unsigned int hist[256];
    __shared__ unsigned long long gtlist[32];
    __shared__ unsigned int eqlow[64];
    __shared__ unsigned int sc[8];

    int t = threadIdx.x, lane = t & 31;
    int role = blockIdx.x & 1;
    int row  = blockIdx.x >> 1;
    int b    = blockIdx.y;
    hist[t] = 0;
    if (t == 0){ sc[2] = 0; sc[3] = 0; }
    __syncthreads();

    if (role == 0){
        // feature top-k over g_pair row
        const float4* pr = (const float4*)(g_pair + (size_t)b*NPTS*NPTS + (size_t)row*NPTS);
        for (int j = t; j < NPTS/4; j += 256){
            float4 v = __ldg(&pr[j]);
            uint4 o; o.x = f2ord(v.x); o.y = f2ord(v.y); o.z = f2ord(v.z); o.w = f2ord(v.w);
            *(uint4*)&vals[4*j] = o;
            hist_add(hist, o.x, lane);
            hist_add(hist, o.y, lane);
            hist_add(hist, o.z, lane);
            hist_add(hist, o.w, lane);
        }
        int* out = g_idx1 + ((size_t)b*NPTS + row)*KNN;
        top20_select_posthist(vals, hist, gtlist, eqlow, sc, out);
    } else {
        // coordinate KNN: distances + norms computed inline (identical fmaf chains)
        const float* xb = x + (size_t)b*NPTS*3;
        float xr0 = xb[row*3+0], xr1 = xb[row*3+1], xr2 = xb[row*3+2];
        float rn = 0.f;
        rn = fmaf(xr0,xr0,rn); rn = fmaf(xr1,xr1,rn); rn = fmaf(xr2,xr2,rn);
        for (int i = t; i < NPTS; i += 256){
            float m0 = __ldg(&xb[i*3+0]), m1 = __ldg(&xb[i*3+1]), m2 = __ldg(&xb[i*3+2]);
            float s = 0.f;
            s = fmaf(xr0, m0, s); s = fmaf(xr1, m1, s); s = fmaf(xr2, m2, s);
            float cn = 0.f;
            cn = fmaf(m0,m0,cn); cn = fmaf(m1,m1,cn); cn = fmaf(m2,m2,cn);
            unsigned v = f2ord(epi(s, rn, cn));
            vals[i] = v;
            hist_add(hist, v, lane);
        }
        int* out = g_idx2 + ((size_t)b*NPTS + row)*KNN;
        top20_select_posthist(vals, hist, gtlist, eqlow, sc, out);
    }
}

// ---------------- dg precompute: a = (Wc-Wd)@h, u = Wd@h; 8 groups per block ----------------
__global__ void k_dgpre(const float* __restrict__ wdg1)
{
    __shared__ float wct[64*64], wdt[64*64];
    __shared__ float hs[4][64];
    int t = threadIdx.x;
    for (int i = t; i < 4096; i += 256){
        int c = i>>6, k = i&63;
        float wc = wdg1[c*128 + k], wd = wdg1[c*128 + 64 + k];
        wdt[k*64+c] = wd;
        wct[k*64+c] = wc - wd;
    }
    __syncthreads();
    int lp = t>>6, c = t&63;
    float wa[64], wu[64];
    #pragma unroll
    for (int k = 0; k < 64; k++){ wa[k] = wct[k*64+c]; wu[k] = wdt[k*64+c]; }
    for (int g2 = 0; g2 < 8; g2++){
        int p = (blockIdx.x*8 + g2)*4 + lp;
        __syncthreads();
        hs[lp][c] = g_h[p*64+c];
        __syncthreads();
        float sa = 0.f, su = 0.f;
        #pragma unroll
        for (int k = 0; k < 64; k++){ float h = hs[lp][k]; sa += wa[k]*h; su += wu[k]*h; }
        g_a[p*64+c] = sa;
        g_u[p*64+c] = su;
    }
}

// ---------------- dg edge conv, two-phase (4 pts/block, 1 ch/thread) ----------------
__global__ void k_dgedge(const float* __restrict__ w2,
                         const float* __restrict__ g1v, const float* __restrict__ b1v,
                         const float* __restrict__ g2v, const float* __restrict__ b2v)
{
    __shared__ float wt[4096];
    __shared__ float t1s[4][KNN][64];
    __shared__ float sg1[64], sb1[64], sg2[64], sb2[64];
    int t = threadIdx.x;
    for (int i = t; i < 4096; i += 256){ int c = i>>6, k = i&63; wt[k*64+c] = w2[i]; }
    if (t < 64){ sg1[t] = g1v[t]; sb1[t] = b1v[t]; sg2[t] = g2v[t]; sb2[t] = b2v[t]; }
    __syncthreads();
    int lp = t>>6, c = t&63;
    int p    = blockIdx.x*4 + lp;
    int base = (p >> 12) * NPTS;
    float ac = g_a[p*64+c];
    float G1 = sg1[c], B1 = sb1[c], G2 = sg2[c], B2 = sb2[c];
    const int* ip = &g_idx1[p*KNN];
    #pragma unroll 5
    for (int j = 0; j < KNN; j++){
        int m = ip[j];
        float v = (ac + g_u[(base+m)*64 + c]) * G1 + B1;
        t1s[lp][j][c] = lrelu(v);
    }
    float wr[64];
    #pragma unroll
    for (int k = 0; k < 64; k++) wr[k] = wt[k*64+c];
    __syncthreads();
    float mx = -3.4e38f;
    for (int j = 0; j < KNN; j++){
        const float4* tp4 = (const float4*)t1s[lp][j];
        float s = 0.f;
        #pragma unroll
        for (int k4 = 0; k4 < 16; k4++){
            float4 hv = tp4[k4];
            s += wr[4*k4+0]*hv.x + wr[4*k4+1]*hv.y + wr[4*k4+2]*hv.z + wr[4*k4+3]*hv.w;
        }
        s = lrelu(s*G2 + B2);
        mx = fmaxf(mx, s);
    }
    g_hdg[p*64+c] = mx;
}

// ---------------- sn branch: gather-max of per-point MLP output ----------------
__global__ void k_snmax()
{
    int t = threadIdx.x;
    int lp = t>>6, c = t&63;
    int p    = blockIdx.x*4 + lp;
    int base = (p >> 12) * NPTS;
    const int* ip = &g_idx2[p*KNN];
    float mx = -3.4e38f;
    for (int j = 0; j < KNN; j++){
        int m = ip[j];
        mx = fmaxf(mx, g_p2[(base+m)*64 + c]);
    }
    g_hsn[p*64+c] = mx;
}

// ---------------- conv5 GEMM (64x64 tiles, 4x4 per thread) ----------------
__global__ void k_conv5(const float* __restrict__ w5, const float* __restrict__ g5,
                        const float* __restrict__ b5, float* __restrict__ out)
{
    __shared__ float wt[64][68];
    __shared__ float ht[64][68];
    int t   = threadIdx.x;
    int co0 = blockIdx.y*64;
    int pt0 = blockIdx.x*64;
    int tr = (t>>4)<<2, tc = (t&15)<<2;
    float acc[4][4] = {{0.f,0.f,0.f,0.f},{0.f,0.f,0.f,0.f},{0.f,0.f,0.f,0.f},{0.f,0.f,0.f,0.f}};
    for (int kc = 0; kc < 2; kc++){
        __syncthreads();
        for (int i = t; i < 4096; i += 256){ int c = i>>6, k = i&63; wt[k][c] = w5[(co0+c)*128 + kc*64 + k]; }
        for (int i = t; i < 4096; i += 256){ int q = i>>6, k = i&63; ht[k][q] = g_h4[(size_t)(pt0+q)*128 + kc*64 + k]; }
        __syncthreads();
        #pragma unroll
        for (int k = 0; k < 64; k++){
            float4 wv = *(const float4*)&wt[k][tr];
            float4 hv = *(const float4*)&ht[k][tc];
            acc[0][0] += wv.x*hv.x; acc[0][1] += wv.x*hv.y; acc[0][2] += wv.x*hv.z; acc[0][3] += wv.x*hv.w;
            acc[1][0] += wv.y*hv.x; acc[1][1] += wv.y*hv.y; acc[1][2] += wv.y*hv.z; acc[1][3] += wv.y*hv.w;
            acc[2][0] += wv.z*hv.x; acc[2][1] += wv.z*hv.y; acc[2][2] += wv.z*hv.z; acc[2][3] += wv.z*hv.w;
            acc[3][0] += wv.w*hv.x; acc[3][1] += wv.w*hv.y; acc[3][2] += wv.w*hv.z; acc[3][3] += wv.w*hv.w;
        }
    }
    int bI = pt0 >> 12;
    int n0 = (pt0 + tc) & (NPTS-1);
    #pragma unroll
    for (int i = 0; i < 4; i++){
        int co = co0 + tr + i;
        float G = g5[co], Bv = b5[co];
        float4 o;
        o.x = lrelu(acc[i][0]*G + Bv);
        o.y = lrelu(acc[i][1]*G + Bv);
        o.z = lrelu(acc[i][2]*G + Bv);
        o.w = lrelu(acc[i][3]*G + Bv);
        *(float4*)&out[((size_t)bI*512 + co)*NPTS + n0] = o;
    }
}

// ---------------- launch ----------------
extern "C" void kernel_launch(void* const* d_in, const int* in_sizes, int n_in,
                              void* d_out, int out_size)
{
    const float* x    = (const float*)d_in[0];
    const float* w1   = (const float*)d_in[1];
    const float* g1   = (const float*)d_in[2];
    const float* b1   = (const float*)d_in[3];
    const float* w2   = (const float*)d_in[4];
    const float* g2   = (const float*)d_in[5];
    const float* b2   = (const float*)d_in[6];
    const float* wdg1 = (const float*)d_in[7];
    const float* gdg1 = (const float*)d_in[8];
    const float* bdg1 = (const float*)d_in[9];
    const float* wdg2 = (const float*)d_in[10];
    const float* gdg2 = (const float*)d_in[11];
    const float* bdg2 = (const float*)d_in[12];
    const float* wsn1 = (const float*)d_in[13];
    const float* gsn1 = (const float*)d_in[14];
    const float* bsn1 = (const float*)d_in[15];
    const float* wsn2 = (const float*)d_in[16];
    const float* gsn2 = (const float*)d_in[17];
    const float* bsn2 = (const float*)d_in[18];
    const float* w3   = (const float*)d_in[19];
    const float* g3   = (const float*)d_in[20];
    const float* b3   = (const float*)d_in[21];
    const float* w4   = (const float*)d_in[22];
    const float* g4   = (const float*)d_in[23];
    const float* b4   = (const float*)d_in[24];
    const float* w5   = (const float*)d_in[25];
    const float* g5   = (const float*)d_in[26];
    const float* b5   = (const float*)d_in[27];

    float* out  = (float*)d_out;

    const int PAIR_SMEM = 4*32*132*4;   // 67584 B dynamic smem
    static int attr_done = 0;
    if (!attr_done){
        cudaFuncSetAttribute(k_pair, cudaFuncAttributeMaxDynamicSharedMemorySize, PAIR_SMEM);
        attr_done = 1;
    }

    // fused conv1+conv2, then h-norms
    k_conv12<<<TOTPTS/32, 256>>>(x, w1, g1, b1, w2, g2, b2);
    k_norms <<<TOTPTS/256, 256>>>();

    const int NTILE = 32*33/2;   // 528 upper-triangular 128x128 tiles
    // feature pair matrices (all batches)
    k_pair<<<dim3(NTILE, BB), 256, PAIR_SMEM>>>();
    // combined select: interleaved feature top-k (even blocks) + coord KNN (odd blocks)
    k_select<<<dim3(2*NPTS, BB), 256>>>(x);

    // dg branch
    k_dgpre <<<TOTPTS/32, 256>>>(wdg1);
    k_dgedge<<<TOTPTS/4,  256>>>(wdg2, gdg1, bdg1, gdg2, bdg2);

    // sn branch: per-point MLP then gather-max
    k_pconv<64><<<TOTPTS/32, 256>>>(1, wsn1, gsn1, bsn1);
    k_pconv<64><<<TOTPTS/32, 256>>>(2, wsn2, gsn2, bsn2);
    k_snmax    <<<TOTPTS/4,  256>>>();

    // head
    k_pconv<64> <<<TOTPTS/32, 256>>>(3, w3, g3, b3);
    k_pconv<128><<<TOTPTS/16, 256>>>(4, w4, g4, b4);
    k_conv5     <<<dim3(TOTPTS/64, 512/64), 256>>>(w5, g5, b5, out);
}